// round 1
// baseline (speedup 1.0000x reference)
#include <cuda_runtime.h>
#include <math.h>

#define NLAYER 12
#define BATCH  4
#define SEQ    1024
#define CH     1024
#define NH     16
#define HD     64
#define MROWS  (BATCH*SEQ)   // 4096
#define LNEPS  1e-5f

// ---------------- scratch (static device memory; no allocs allowed) ----------
__device__ float g_x[MROWS*CH];                       // residual stream, 16MB
__device__ float g_ln[MROWS*CH];                      // layernorm output, 16MB
__device__ float g_qkv[MROWS*3*CH];                   // qkv, 48MB
__device__ float g_att[(size_t)BATCH*NH*SEQ*SEQ];     // attention matrix, 256MB
__device__ float g_y[MROWS*CH];                       // attn output, 16MB
__device__ float g_fc[(size_t)MROWS*4*CH];            // mlp hidden, 64MB

// ---------------- simple copy ------------------------------------------------
__global__ void copy_k(const float* __restrict__ in, float* __restrict__ out, int n) {
    int i = blockIdx.x * blockDim.x + threadIdx.x;
    if (i < n) out[i] = in[i];
}

// ---------------- layernorm: one block per row -------------------------------
__global__ void ln_k(const float* __restrict__ in, const float* __restrict__ gam,
                     const float* __restrict__ bet, float* __restrict__ out) {
    int row = blockIdx.x;
    const float* p = in + (size_t)row * CH;
    float s = 0.f, s2 = 0.f;
    for (int c = threadIdx.x; c < CH; c += blockDim.x) {
        float v = p[c];
        s += v; s2 += v * v;
    }
    __shared__ float sh[16];
    #pragma unroll
    for (int o = 16; o > 0; o >>= 1) {
        s  += __shfl_down_sync(0xffffffffu, s, o);
        s2 += __shfl_down_sync(0xffffffffu, s2, o);
    }
    int lane = threadIdx.x & 31, w = threadIdx.x >> 5;
    if (lane == 0) { sh[w] = s; sh[8 + w] = s2; }
    __syncthreads();
    if (threadIdx.x == 0) {
        float a = 0.f, b = 0.f;
        #pragma unroll
        for (int i = 0; i < 8; i++) { a += sh[i]; b += sh[8 + i]; }
        sh[0] = a; sh[8] = b;
    }
    __syncthreads();
    float mean = sh[0] * (1.f / CH);
    float var  = sh[8] * (1.f / CH) - mean * mean;
    float rstd = rsqrtf(var + LNEPS);
    float* o = out + (size_t)row * CH;
    for (int c = threadIdx.x; c < CH; c += blockDim.x)
        o[c] = (p[c] - mean) * rstd * gam[c] + bet[c];
}

// ---------------- SGEMM 128x128x8, 256 thr, 8x8/thread, double-buffered ------
// C[M,N] = A[M,K] @ B[K,N] + bias (+ GELU) (+ residual)
template<bool DO_GELU, bool DO_RES>
__global__ void __launch_bounds__(256) sgemm_k(
    const float* __restrict__ A, const float* __restrict__ Bw,
    const float* __restrict__ bias, const float* __restrict__ Res,
    float* __restrict__ Cout, int Md, int N, int K)
{
    __shared__ float As[2][8][128];
    __shared__ float Bs[2][8][128];
    const int tid  = threadIdx.x;
    const int row0 = blockIdx.y * 128;
    const int col0 = blockIdx.x * 128;
    const int tr = (tid >> 4) << 3;   // 0..120 step 8
    const int tc = (tid & 15) << 3;
    const int arow = tid >> 1, acol = (tid & 1) << 2;
    const int brow = tid >> 5, bcol = (tid & 31) << 2;
    const float* Ag = A  + (size_t)(row0 + arow) * K + acol;
    const float* Bg = Bw + (size_t)brow * N + col0 + bcol;

    float acc[8][8];
    #pragma unroll
    for (int i = 0; i < 8; i++)
        #pragma unroll
        for (int j = 0; j < 8; j++) acc[i][j] = 0.f;

    {   // prologue: load k-tile 0 into buffer 0
        float4 va = *(const float4*)Ag;
        As[0][acol+0][arow] = va.x; As[0][acol+1][arow] = va.y;
        As[0][acol+2][arow] = va.z; As[0][acol+3][arow] = va.w;
        *(float4*)&Bs[0][brow][bcol] = *(const float4*)Bg;
    }
    __syncthreads();

    const int nk = K >> 3;
    for (int kt = 0; kt < nk; kt++) {
        const int buf = kt & 1;
        if (kt + 1 < nk) {
            const int nb = buf ^ 1;
            float4 va = *(const float4*)(Ag + (kt + 1) * 8);
            float4 vb = *(const float4*)(Bg + (size_t)(kt + 1) * 8 * N);
            As[nb][acol+0][arow] = va.x; As[nb][acol+1][arow] = va.y;
            As[nb][acol+2][arow] = va.z; As[nb][acol+3][arow] = va.w;
            *(float4*)&Bs[nb][brow][bcol] = vb;
        }
        #pragma unroll
        for (int k = 0; k < 8; k++) {
            float a[8], b[8];
            *(float4*)&a[0] = *(const float4*)&As[buf][k][tr];
            *(float4*)&a[4] = *(const float4*)&As[buf][k][tr + 4];
            *(float4*)&b[0] = *(const float4*)&Bs[buf][k][tc];
            *(float4*)&b[4] = *(const float4*)&Bs[buf][k][tc + 4];
            #pragma unroll
            for (int i = 0; i < 8; i++)
                #pragma unroll
                for (int j = 0; j < 8; j++)
                    acc[i][j] = fmaf(a[i], b[j], acc[i][j]);
        }
        __syncthreads();
    }

    // epilogue: bias (+gelu) (+residual), vectorized stores
    #pragma unroll
    for (int i = 0; i < 8; i++) {
        const size_t r = (size_t)(row0 + tr + i);
        float vv[8];
        #pragma unroll
        for (int j = 0; j < 8; j++) {
            float v = acc[i][j] + bias[col0 + tc + j];
            if (DO_GELU) {
                const float kk = 0.7978845608028654f;
                v = 0.5f * v * (1.f + tanhf(kk * (v + 0.044715f * v * v * v)));
            }
            vv[j] = v;
        }
        float* dst = Cout + r * N + col0 + tc;
        if (DO_RES) {
            const float* rs = Res + r * N + col0 + tc;
            float4 r0 = *(const float4*)rs;
            float4 r1 = *(const float4*)(rs + 4);
            vv[0] += r0.x; vv[1] += r0.y; vv[2] += r0.z; vv[3] += r0.w;
            vv[4] += r1.x; vv[5] += r1.y; vv[6] += r1.z; vv[7] += r1.w;
        }
        *(float4*)dst       = make_float4(vv[0], vv[1], vv[2], vv[3]);
        *(float4*)(dst + 4) = make_float4(vv[4], vv[5], vv[6], vv[7]);
    }
}

// ---------------- attention scores: att = (Q @ K^T) * scale, causal ----------
// grid: (kTile=16, qTile=16, B*H).  Blocks with kt > qt fully masked -> skip.
__global__ void __launch_bounds__(256) attn_scores_k(
    const float* __restrict__ qkv, float* __restrict__ att)
{
    const int bh = blockIdx.z;
    const int b  = bh / NH, h = bh % NH;
    const int qt = blockIdx.y, kt = blockIdx.x;
    if (kt > qt) return;

    __shared__ float Qs[HD][65];
    __shared__ float Ks[HD][65];
    const int tid = threadIdx.x;
    const int q0 = qt * 64, k0 = kt * 64;
    const float* Qg = qkv + ((size_t)(b * SEQ + q0)) * 3 * CH + h * HD;
    const float* Kg = qkv + ((size_t)(b * SEQ + k0)) * 3 * CH + CH + h * HD;

    for (int i = tid; i < 64 * 16; i += 256) {   // 64 rows x 16 float4
        int r = i >> 4, c4 = (i & 15) << 2;
        float4 v = *(const float4*)(Qg + (size_t)r * 3 * CH + c4);
        Qs[c4+0][r] = v.x; Qs[c4+1][r] = v.y; Qs[c4+2][r] = v.z; Qs[c4+3][r] = v.w;
        float4 w = *(const float4*)(Kg + (size_t)r * 3 * CH + c4);
        Ks[c4+0][r] = w.x; Ks[c4+1][r] = w.y; Ks[c4+2][r] = w.z; Ks[c4+3][r] = w.w;
    }
    __syncthreads();

    const int trr = (tid >> 4) << 2;   // 0..60
    const int tcc = (tid & 15) << 2;
    float acc[4][4] = {};
    #pragma unroll 8
    for (int d = 0; d < HD; d++) {
        float a0 = Qs[d][trr], a1 = Qs[d][trr+1], a2 = Qs[d][trr+2], a3 = Qs[d][trr+3];
        float b0 = Ks[d][tcc], b1 = Ks[d][tcc+1], b2 = Ks[d][tcc+2], b3 = Ks[d][tcc+3];
        acc[0][0] = fmaf(a0,b0,acc[0][0]); acc[0][1] = fmaf(a0,b1,acc[0][1]);
        acc[0][2] = fmaf(a0,b2,acc[0][2]); acc[0][3] = fmaf(a0,b3,acc[0][3]);
        acc[1][0] = fmaf(a1,b0,acc[1][0]); acc[1][1] = fmaf(a1,b1,acc[1][1]);
        acc[1][2] = fmaf(a1,b2,acc[1][2]); acc[1][3] = fmaf(a1,b3,acc[1][3]);
        acc[2][0] = fmaf(a2,b0,acc[2][0]); acc[2][1] = fmaf(a2,b1,acc[2][1]);
        acc[2][2] = fmaf(a2,b2,acc[2][2]); acc[2][3] = fmaf(a2,b3,acc[2][3]);
        acc[3][0] = fmaf(a3,b0,acc[3][0]); acc[3][1] = fmaf(a3,b1,acc[3][1]);
        acc[3][2] = fmaf(a3,b2,acc[3][2]); acc[3][3] = fmaf(a3,b3,acc[3][3]);
    }
    const float scale = 0.125f;  // 1/sqrt(64)
    #pragma unroll
    for (int i = 0; i < 4; i++) {
        int q = q0 + trr + i;
        #pragma unroll
        for (int j = 0; j < 4; j++) {
            int k = k0 + tcc + j;
            if (k <= q)
                att[((size_t)bh * SEQ + q) * SEQ + k] = acc[i][j] * scale;
        }
    }
}

// ---------------- causal softmax: one block per row --------------------------
// Writes normalized probs for k<=q, exact zeros for k>q (so att@V is dense).
__global__ void softmax_k(float* __restrict__ att) {
    const int row = blockIdx.x;              // b*H*T rows
    const int q = row & (SEQ - 1);
    float* p = att + (size_t)row * SEQ;
    const int n = q + 1;
    const int tid = threadIdx.x;

    float m = -1e30f;
    for (int j = tid; j < n; j += blockDim.x) m = fmaxf(m, p[j]);
    __shared__ float shm[4], shs[4];
    #pragma unroll
    for (int o = 16; o > 0; o >>= 1) m = fmaxf(m, __shfl_xor_sync(0xffffffffu, m, o));
    if ((tid & 31) == 0) shm[tid >> 5] = m;
    __syncthreads();
    m = fmaxf(fmaxf(shm[0], shm[1]), fmaxf(shm[2], shm[3]));

    float s = 0.f;
    for (int j = tid; j < n; j += blockDim.x) {
        float e = __expf(p[j] - m);
        p[j] = e; s += e;
    }
    #pragma unroll
    for (int o = 16; o > 0; o >>= 1) s += __shfl_xor_sync(0xffffffffu, s, o);
    if ((tid & 31) == 0) shs[tid >> 5] = s;
    __syncthreads();
    s = shs[0] + shs[1] + shs[2] + shs[3];
    float inv = 1.f / s;
    for (int j = tid; j < n; j += blockDim.x) p[j] *= inv;
    for (int j = n + tid; j < SEQ; j += blockDim.x) p[j] = 0.f;
}

// ---------------- att @ V ----------------------------------------------------
// y[b, q, h*64+d] = sum_k att[bh,q,k] * V[b,k,h*64+d]; k-range causally truncated.
__global__ void __launch_bounds__(256) attn_v_k(
    const float* __restrict__ att, const float* __restrict__ qkv,
    float* __restrict__ y)
{
    const int bh = blockIdx.z;
    const int b = bh / NH, h = bh % NH;
    const int qt = blockIdx.y;
    const int q0 = qt * 64;
    const int tid = threadIdx.x;

    __shared__ float As[64][33];
    __shared__ float Vs[32][65];
    const int trr = (tid >> 4) << 2;
    const int tcc = (tid & 15) << 2;
    float acc[4][4] = {};

    const float* attb = att + ((size_t)bh * SEQ + q0) * SEQ;
    const float* Vg = qkv + (size_t)b * SEQ * 3 * CH + 2 * CH + h * HD;

    const int nkt = 2 * (qt + 1);   // k-tiles of 32, covering k <= q0+63
    for (int kt = 0; kt < nkt; kt++) {
        for (int i = tid; i < 2048; i += 256) {   // att tile 64x32
            int r = i >> 5, c = i & 31;
            As[r][c] = attb[(size_t)r * SEQ + kt * 32 + c];
        }
        for (int i = tid; i < 2048; i += 256) {   // V tile 32x64
            int r = i >> 6, c = i & 63;
            Vs[r][c] = Vg[(size_t)(kt * 32 + r) * 3 * CH + c];
        }
        __syncthreads();
        #pragma unroll 8
        for (int k = 0; k < 32; k++) {
            float a0 = As[trr][k], a1 = As[trr+1][k], a2 = As[trr+2][k], a3 = As[trr+3][k];
            float b0 = Vs[k][tcc], b1 = Vs[k][tcc+1], b2 = Vs[k][tcc+2], b3 = Vs[k][tcc+3];
            acc[0][0] = fmaf(a0,b0,acc[0][0]); acc[0][1] = fmaf(a0,b1,acc[0][1]);
            acc[0][2] = fmaf(a0,b2,acc[0][2]); acc[0][3] = fmaf(a0,b3,acc[0][3]);
            acc[1][0] = fmaf(a1,b0,acc[1][0]); acc[1][1] = fmaf(a1,b1,acc[1][1]);
            acc[1][2] = fmaf(a1,b2,acc[1][2]); acc[1][3] = fmaf(a1,b3,acc[1][3]);
            acc[2][0] = fmaf(a2,b0,acc[2][0]); acc[2][1] = fmaf(a2,b1,acc[2][1]);
            acc[2][2] = fmaf(a2,b2,acc[2][2]); acc[2][3] = fmaf(a2,b3,acc[2][3]);
            acc[3][0] = fmaf(a3,b0,acc[3][0]); acc[3][1] = fmaf(a3,b1,acc[3][1]);
            acc[3][2] = fmaf(a3,b2,acc[3][2]); acc[3][3] = fmaf(a3,b3,acc[3][3]);
        }
        __syncthreads();
    }
    #pragma unroll
    for (int i = 0; i < 4; i++) {
        size_t r = (size_t)(b * SEQ + q0 + trr + i);
        #pragma unroll
        for (int j = 0; j < 4; j++)
            y[r * CH + h * HD + tcc + j] = acc[i][j];
    }
}

// ---------------- host launcher ----------------------------------------------
extern "C" void kernel_launch(void* const* d_in, const int* in_sizes, int n_in,
                              void* d_out, int out_size)
{
    const float* x     = (const float*)d_in[0];
    const float* ln1g  = (const float*)d_in[1];
    const float* ln1b  = (const float*)d_in[2];
    const float* attw  = (const float*)d_in[3];
    const float* attb  = (const float*)d_in[4];
    const float* projw = (const float*)d_in[5];
    const float* projb = (const float*)d_in[6];
    const float* ln2g  = (const float*)d_in[7];
    const float* ln2b  = (const float*)d_in[8];
    const float* fcw   = (const float*)d_in[9];
    const float* fcb   = (const float*)d_in[10];
    const float* fc2w  = (const float*)d_in[11];
    const float* fc2b  = (const float*)d_in[12];
    const float* lnfg  = (const float*)d_in[13];
    const float* lnfb  = (const float*)d_in[14];

    float *px, *pln, *pqkv, *patt, *py, *pfc;
    cudaGetSymbolAddress((void**)&px,   g_x);
    cudaGetSymbolAddress((void**)&pln,  g_ln);
    cudaGetSymbolAddress((void**)&pqkv, g_qkv);
    cudaGetSymbolAddress((void**)&patt, g_att);
    cudaGetSymbolAddress((void**)&py,   g_y);
    cudaGetSymbolAddress((void**)&pfc,  g_fc);

    copy_k<<<(MROWS * CH + 255) / 256, 256>>>(x, px, MROWS * CH);

    for (int l = 0; l < NLAYER; l++) {
        // ln1
        ln_k<<<MROWS, 256>>>(px, ln1g + l * CH, ln1b + l * CH, pln);
        // qkv = ln1 @ attn_w + attn_b
        sgemm_k<false, false><<<dim3(3 * CH / 128, MROWS / 128), 256>>>(
            pln, attw + (size_t)l * CH * 3 * CH, attb + (size_t)l * 3 * CH,
            nullptr, pqkv, MROWS, 3 * CH, CH);
        // att = causal softmax(Q K^T / sqrt(D))
        attn_scores_k<<<dim3(SEQ / 64, SEQ / 64, BATCH * NH), 256>>>(pqkv, patt);
        softmax_k<<<BATCH * NH * SEQ, 128>>>(patt);
        // y = att @ V
        attn_v_k<<<dim3(1, SEQ / 64, BATCH * NH), 256>>>(patt, pqkv, py);
        // x = x + y @ proj_w + proj_b
        sgemm_k<false, true><<<dim3(CH / 128, MROWS / 128), 256>>>(
            py, projw + (size_t)l * CH * CH, projb + (size_t)l * CH,
            px, px, MROWS, CH, CH);
        // ln2
        ln_k<<<MROWS, 256>>>(px, ln2g + l * CH, ln2b + l * CH, pln);
        // h = gelu(ln2 @ fc_w + fc_b)
        sgemm_k<true, false><<<dim3(4 * CH / 128, MROWS / 128), 256>>>(
            pln, fcw + (size_t)l * CH * 4 * CH, fcb + (size_t)l * 4 * CH,
            nullptr, pfc, MROWS, 4 * CH, CH);
        // x = x + h @ fc2_w + fc2_b
        sgemm_k<false, true><<<dim3(CH / 128, MROWS / 128), 256>>>(
            pfc, fc2w + (size_t)l * 4 * CH * CH, fc2b + (size_t)l * CH,
            px, px, MROWS, CH, 4 * CH);
    }
    // final layernorm -> output
    ln_k<<<MROWS, 256>>>(px, lnfg, lnfb, (float*)d_out);
}

// round 3
// speedup vs baseline: 1.1702x; 1.1702x over previous
#include <cuda_runtime.h>
#include <math.h>

#define NLAYER 12
#define BATCH  4
#define SEQ    1024
#define CH     1024
#define NH     16
#define HD     64
#define MROWS  (BATCH*SEQ)   // 4096
#define LNEPS  1e-5f
#define LDA    140           // smem pitch (words); 140 % 32 == 12 -> conflict-free frags
#define LDV    76            // 76 % 32 == 12

// ---------------- scratch (static device memory; no allocs allowed) ----------
__device__ float g_x[MROWS*CH];
__device__ float g_ln[MROWS*CH];
__device__ float g_qkv[MROWS*3*CH];
__device__ float g_att[(size_t)BATCH*NH*SEQ*SEQ];
__device__ float g_y[MROWS*CH];
__device__ float g_fc[(size_t)MROWS*4*CH];

// ---------------- helpers ----------------------------------------------------
__device__ __forceinline__ unsigned f2tf32(float f) {
    unsigned u; asm("cvt.rna.tf32.f32 %0, %1;" : "=r"(u) : "f"(f)); return u;
}
__device__ __forceinline__ void split_tf32(float v, unsigned& hi, unsigned& lo) {
    hi = f2tf32(v);
    lo = f2tf32(v - __uint_as_float(hi));
}
__device__ __forceinline__ void mma_tf32(float* c, const unsigned* a, const unsigned* b) {
    asm volatile("mma.sync.aligned.m16n8k8.row.col.f32.tf32.tf32.f32 "
        "{%0,%1,%2,%3}, {%4,%5,%6,%7}, {%8,%9}, {%0,%1,%2,%3};\n"
        : "+f"(c[0]), "+f"(c[1]), "+f"(c[2]), "+f"(c[3])
        : "r"(a[0]), "r"(a[1]), "r"(a[2]), "r"(a[3]), "r"(b[0]), "r"(b[1]));
}
__device__ __forceinline__ float gelu1(float v) {
    const float kk = 0.7978845608028654f;
    return 0.5f * v * (1.f + tanhf(kk * (v + 0.044715f * v * v * v)));
}

// ---------------- simple copy ------------------------------------------------
__global__ void copy_k(const float* __restrict__ in, float* __restrict__ out, int n) {
    int i = blockIdx.x * blockDim.x + threadIdx.x;
    if (i < n) out[i] = in[i];
}

// ---------------- layernorm: one block per row -------------------------------
__global__ void ln_k(const float* __restrict__ in, const float* __restrict__ gam,
                     const float* __restrict__ bet, float* __restrict__ out) {
    int row = blockIdx.x;
    const float* p = in + (size_t)row * CH;
    float s = 0.f, s2 = 0.f;
    for (int c = threadIdx.x; c < CH; c += blockDim.x) {
        float v = p[c];
        s += v; s2 += v * v;
    }
    __shared__ float sh[16];
    #pragma unroll
    for (int o = 16; o > 0; o >>= 1) {
        s  += __shfl_down_sync(0xffffffffu, s, o);
        s2 += __shfl_down_sync(0xffffffffu, s2, o);
    }
    int lane = threadIdx.x & 31, w = threadIdx.x >> 5;
    if (lane == 0) { sh[w] = s; sh[8 + w] = s2; }
    __syncthreads();
    if (threadIdx.x == 0) {
        float a = 0.f, b = 0.f;
        #pragma unroll
        for (int i = 0; i < 8; i++) { a += sh[i]; b += sh[8 + i]; }
        sh[0] = a; sh[8] = b;
    }
    __syncthreads();
    float mean = sh[0] * (1.f / CH);
    float var  = sh[8] * (1.f / CH) - mean * mean;
    float rstd = rsqrtf(var + LNEPS);
    float* o = out + (size_t)row * CH;
    for (int c = threadIdx.x; c < CH; c += blockDim.x)
        o[c] = (p[c] - mean) * rstd * gam[c] + bet[c];
}

// ---------------- 3xTF32 tensor-core GEMM ------------------------------------
// C[M,N] = A[M,K] @ B[K,N] + bias (+GELU) (+Res).  128x128 block, BK=16,
// 8 warps (2x4), warp tile 64x32 of m16n8k8 mma.  fp32 staged in smem; hi/lo
// tf32 split done in registers (3 mma per tile pair -> fp32-class accuracy).
template<bool DO_GELU, bool DO_RES>
__global__ void __launch_bounds__(256) gemm3t(
    const float* __restrict__ A, const float* __restrict__ Bw,
    const float* __restrict__ bias, const float* __restrict__ Res,
    float* __restrict__ C, int N, int K)
{
    __shared__ float As[2][16][LDA];
    __shared__ float Bs[2][16][LDA];
    const int tid = threadIdx.x;
    const int row0 = blockIdx.y * 128, col0 = blockIdx.x * 128;
    const int warp = tid >> 5, lane = tid & 31;
    const int wm = warp >> 2, wn = warp & 3;      // 2 x 4 warps
    const int g = lane >> 2, tg = lane & 3;
    const int ar = tid >> 2, ac = (tid & 3) << 2; // A loader rows ar, ar+64
    const int br = tid >> 5, bc = (tid & 31) << 2;// B loader rows br, br+8
    const float* Ag = A  + (size_t)(row0 + ar) * K + ac;
    const float* Bg = Bw + (size_t)br * N + col0 + bc;

    float acc[4][4][4] = {};

    {   // prologue tile 0
        float4 v0 = *(const float4*)Ag;
        float4 v1 = *(const float4*)(Ag + (size_t)64 * K);
        As[0][ac+0][ar] = v0.x; As[0][ac+1][ar] = v0.y;
        As[0][ac+2][ar] = v0.z; As[0][ac+3][ar] = v0.w;
        As[0][ac+0][ar+64] = v1.x; As[0][ac+1][ar+64] = v1.y;
        As[0][ac+2][ar+64] = v1.z; As[0][ac+3][ar+64] = v1.w;
        *(float4*)&Bs[0][br][bc]     = *(const float4*)Bg;
        *(float4*)&Bs[0][br+8][bc]   = *(const float4*)(Bg + (size_t)8 * N);
    }
    __syncthreads();

    const int nk = K >> 4;
    for (int kt = 0; kt < nk; kt++) {
        const int buf = kt & 1;
        if (kt + 1 < nk) {
            const int nb = buf ^ 1;
            const float* a0 = Ag + (kt + 1) * 16;
            float4 v0 = *(const float4*)a0;
            float4 v1 = *(const float4*)(a0 + (size_t)64 * K);
            As[nb][ac+0][ar] = v0.x; As[nb][ac+1][ar] = v0.y;
            As[nb][ac+2][ar] = v0.z; As[nb][ac+3][ar] = v0.w;
            As[nb][ac+0][ar+64] = v1.x; As[nb][ac+1][ar+64] = v1.y;
            As[nb][ac+2][ar+64] = v1.z; As[nb][ac+3][ar+64] = v1.w;
            const float* b0 = Bg + (size_t)(kt + 1) * 16 * N;
            *(float4*)&Bs[nb][br][bc]   = *(const float4*)b0;
            *(float4*)&Bs[nb][br+8][bc] = *(const float4*)(b0 + (size_t)8 * N);
        }
        #pragma unroll
        for (int ks = 0; ks < 2; ks++) {
            const int k0 = ks * 8;
            unsigned ah[4][4], al[4][4], bh[4][2], bl[4][2];
            #pragma unroll
            for (int mi = 0; mi < 4; mi++) {
                const int m0 = wm * 64 + mi * 16;
                split_tf32(As[buf][k0+tg  ][m0+g  ], ah[mi][0], al[mi][0]);
                split_tf32(As[buf][k0+tg  ][m0+g+8], ah[mi][1], al[mi][1]);
                split_tf32(As[buf][k0+tg+4][m0+g  ], ah[mi][2], al[mi][2]);
                split_tf32(As[buf][k0+tg+4][m0+g+8], ah[mi][3], al[mi][3]);
            }
            #pragma unroll
            for (int ni = 0; ni < 4; ni++) {
                const int n0 = wn * 32 + ni * 8;
                split_tf32(Bs[buf][k0+tg  ][n0+g], bh[ni][0], bl[ni][0]);
                split_tf32(Bs[buf][k0+tg+4][n0+g], bh[ni][1], bl[ni][1]);
            }
            #pragma unroll
            for (int mi = 0; mi < 4; mi++)
                #pragma unroll
                for (int ni = 0; ni < 4; ni++) {
                    mma_tf32(acc[mi][ni], ah[mi], bh[ni]);
                    mma_tf32(acc[mi][ni], ah[mi], bl[ni]);
                    mma_tf32(acc[mi][ni], al[mi], bh[ni]);
                }
        }
        __syncthreads();
    }

    // epilogue
    #pragma unroll
    for (int mi = 0; mi < 4; mi++) {
        #pragma unroll
        for (int p = 0; p < 2; p++) {
            const size_t r = (size_t)(row0 + wm * 64 + mi * 16 + g + p * 8);
            float* crow = C + r * N;
            #pragma unroll
            for (int ni = 0; ni < 4; ni++) {
                const int col = col0 + wn * 32 + ni * 8 + 2 * tg;
                float2 bv = *(const float2*)(bias + col);
                float v0 = acc[mi][ni][2*p+0] + bv.x;
                float v1 = acc[mi][ni][2*p+1] + bv.y;
                if (DO_GELU) { v0 = gelu1(v0); v1 = gelu1(v1); }
                if (DO_RES) {
                    float2 rv = *(const float2*)(Res + r * N + col);
                    v0 += rv.x; v1 += rv.y;
                }
                *(float2*)(crow + col) = make_float2(v0, v1);
            }
        }
    }
}

// ---------------- attention scores (3xTF32 mma, causal tile skip) ------------
// att[bh,q,k] = sum_d Q[q,d]*K[k,d] * 0.125.  Block = 128x128 tile.
__global__ void __launch_bounds__(256) attn_scores_tc(
    const float* __restrict__ qkv, float* __restrict__ att)
{
    const int bh = blockIdx.z, b = bh >> 4, h = bh & 15;
    const int qt = blockIdx.y, kt = blockIdx.x;
    if (kt > qt) return;

    __shared__ float Qs[2][16][LDA];
    __shared__ float Ks[2][16][LDA];
    const int tid = threadIdx.x;
    const int warp = tid >> 5, lane = tid & 31;
    const int wm = warp >> 2, wn = warp & 3;
    const int g = lane >> 2, tg = lane & 3;
    const int ar = tid >> 2, ac = (tid & 3) << 2;
    const size_t rstride = (size_t)64 * 3 * CH;
    const float* Qg = qkv + (size_t)(b * SEQ + qt * 128 + ar) * 3 * CH + h * HD + ac;
    const float* Kg = qkv + (size_t)(b * SEQ + kt * 128 + ar) * 3 * CH + CH + h * HD + ac;

    float acc[4][4][4] = {};

    {
        float4 v0 = *(const float4*)Qg;
        float4 v1 = *(const float4*)(Qg + rstride);
        Qs[0][ac+0][ar] = v0.x; Qs[0][ac+1][ar] = v0.y;
        Qs[0][ac+2][ar] = v0.z; Qs[0][ac+3][ar] = v0.w;
        Qs[0][ac+0][ar+64] = v1.x; Qs[0][ac+1][ar+64] = v1.y;
        Qs[0][ac+2][ar+64] = v1.z; Qs[0][ac+3][ar+64] = v1.w;
        float4 w0 = *(const float4*)Kg;
        float4 w1 = *(const float4*)(Kg + rstride);
        Ks[0][ac+0][ar] = w0.x; Ks[0][ac+1][ar] = w0.y;
        Ks[0][ac+2][ar] = w0.z; Ks[0][ac+3][ar] = w0.w;
        Ks[0][ac+0][ar+64] = w1.x; Ks[0][ac+1][ar+64] = w1.y;
        Ks[0][ac+2][ar+64] = w1.z; Ks[0][ac+3][ar+64] = w1.w;
    }
    __syncthreads();

    const int nk = HD / 16;   // 4
    for (int dt = 0; dt < nk; dt++) {
        const int buf = dt & 1;
        if (dt + 1 < nk) {
            const int nb = buf ^ 1;
            const float* q0 = Qg + (dt + 1) * 16;
            float4 v0 = *(const float4*)q0;
            float4 v1 = *(const float4*)(q0 + rstride);
            Qs[nb][ac+0][ar] = v0.x; Qs[nb][ac+1][ar] = v0.y;
            Qs[nb][ac+2][ar] = v0.z; Qs[nb][ac+3][ar] = v0.w;
            Qs[nb][ac+0][ar+64] = v1.x; Qs[nb][ac+1][ar+64] = v1.y;
            Qs[nb][ac+2][ar+64] = v1.z; Qs[nb][ac+3][ar+64] = v1.w;
            const float* kk0 = Kg + (dt + 1) * 16;
            float4 w0 = *(const float4*)kk0;
            float4 w1 = *(const float4*)(kk0 + rstride);
            Ks[nb][ac+0][ar] = w0.x; Ks[nb][ac+1][ar] = w0.y;
            Ks[nb][ac+2][ar] = w0.z; Ks[nb][ac+3][ar] = w0.w;
            Ks[nb][ac+0][ar+64] = w1.x; Ks[nb][ac+1][ar+64] = w1.y;
            Ks[nb][ac+2][ar+64] = w1.z; Ks[nb][ac+3][ar+64] = w1.w;
        }
        #pragma unroll
        for (int ks = 0; ks < 2; ks++) {
            const int k0 = ks * 8;
            unsigned ah[4][4], al[4][4], bh[4][2], bl[4][2];
            #pragma unroll
            for (int mi = 0; mi < 4; mi++) {
                const int m0 = wm * 64 + mi * 16;
                split_tf32(Qs[buf][k0+tg  ][m0+g  ], ah[mi][0], al[mi][0]);
                split_tf32(Qs[buf][k0+tg  ][m0+g+8], ah[mi][1], al[mi][1]);
                split_tf32(Qs[buf][k0+tg+4][m0+g  ], ah[mi][2], al[mi][2]);
                split_tf32(Qs[buf][k0+tg+4][m0+g+8], ah[mi][3], al[mi][3]);
            }
            #pragma unroll
            for (int ni = 0; ni < 4; ni++) {
                const int n0 = wn * 32 + ni * 8;
                split_tf32(Ks[buf][k0+tg  ][n0+g], bh[ni][0], bl[ni][0]);
                split_tf32(Ks[buf][k0+tg+4][n0+g], bh[ni][1], bl[ni][1]);
            }
            #pragma unroll
            for (int mi = 0; mi < 4; mi++)
                #pragma unroll
                for (int ni = 0; ni < 4; ni++) {
                    mma_tf32(acc[mi][ni], ah[mi], bh[ni]);
                    mma_tf32(acc[mi][ni], ah[mi], bl[ni]);
                    mma_tf32(acc[mi][ni], al[mi], bh[ni]);
                }
        }
        __syncthreads();
    }

    const bool diag = (qt == kt);
    const float scale = 0.125f;   // 1/sqrt(64)
    #pragma unroll
    for (int mi = 0; mi < 4; mi++) {
        #pragma unroll
        for (int p = 0; p < 2; p++) {
            const int q = qt * 128 + wm * 64 + mi * 16 + g + p * 8;
            float* rowp = att + ((size_t)bh * SEQ + q) * SEQ + kt * 128;
            #pragma unroll
            for (int ni = 0; ni < 4; ni++) {
                const int kc = wn * 32 + ni * 8 + 2 * tg;
                float v0 = acc[mi][ni][2*p+0] * scale;
                float v1 = acc[mi][ni][2*p+1] * scale;
                if (!diag) {
                    *(float2*)(rowp + kc) = make_float2(v0, v1);
                } else {
                    const int kg = kt * 128 + kc;
                    if (kg     <= q) rowp[kc]     = v0;
                    if (kg + 1 <= q) rowp[kc + 1] = v1;
                }
            }
        }
    }
}

// ---------------- causal softmax ---------------------------------------------
__global__ void softmax_k(float* __restrict__ att) {
    const int row = blockIdx.x;
    const int q = row & (SEQ - 1);
    float* p = att + (size_t)row * SEQ;
    const int n = q + 1;
    const int tid = threadIdx.x;

    float m = -1e30f;
    for (int j = tid; j < n; j += blockDim.x) m = fmaxf(m, p[j]);
    __shared__ float shm[4], shs[4];
    #pragma unroll
    for (int o = 16; o > 0; o >>= 1) m = fmaxf(m, __shfl_xor_sync(0xffffffffu, m, o));
    if ((tid & 31) == 0) shm[tid >> 5] = m;
    __syncthreads();
    m = fmaxf(fmaxf(shm[0], shm[1]), fmaxf(shm[2], shm[3]));

    float s = 0.f;
    for (int j = tid; j < n; j += blockDim.x) {
        float e = __expf(p[j] - m);
        p[j] = e; s += e;
    }
    #pragma unroll
    for (int o = 16; o > 0; o >>= 1) s += __shfl_xor_sync(0xffffffffu, s, o);
    if ((tid & 31) == 0) shs[tid >> 5] = s;
    __syncthreads();
    s = shs[0] + shs[1] + shs[2] + shs[3];
    float inv = 1.f / s;
    for (int j = tid; j < n; j += blockDim.x) p[j] *= inv;
    for (int j = n + tid; j < SEQ; j += blockDim.x) p[j] = 0.f;
}

// ---------------- att @ V (3xTF32 mma) ---------------------------------------
// Block = 128 q-rows x 64 d-cols (one head).  8 warps (4x2), warp tile 32x32.
__global__ void __launch_bounds__(256) attn_v_tc(
    const float* __restrict__ att, const float* __restrict__ qkv,
    float* __restrict__ y)
{
    const int qt = blockIdx.x, bh = blockIdx.y;
    const int b = bh >> 4, h = bh & 15;
    __shared__ float As[2][16][LDA];
    __shared__ float Vs[2][16][LDV];
    const int tid = threadIdx.x;
    const int warp = tid >> 5, lane = tid & 31;
    const int wm = warp >> 1, wn = warp & 1;      // 4 x 2 warps
    const int g = lane >> 2, tg = lane & 3;
    const int ar = tid >> 2, ac = (tid & 3) << 2;
    const int vr = tid >> 4, vc = (tid & 15) << 2;
    const float* Ag = att + ((size_t)bh * SEQ + qt * 128 + ar) * SEQ + ac;
    const float* Vg = qkv + (size_t)(b * SEQ + vr) * 3 * CH + 2 * CH + h * HD + vc;
    const size_t vstride = (size_t)16 * 3 * CH;

    float acc[2][4][4] = {};

    {
        float4 v0 = *(const float4*)Ag;
        float4 v1 = *(const float4*)(Ag + (size_t)64 * SEQ);
        As[0][ac+0][ar] = v0.x; As[0][ac+1][ar] = v0.y;
        As[0][ac+2][ar] = v0.z; As[0][ac+3][ar] = v0.w;
        As[0][ac+0][ar+64] = v1.x; As[0][ac+1][ar+64] = v1.y;
        As[0][ac+2][ar+64] = v1.z; As[0][ac+3][ar+64] = v1.w;
        *(float4*)&Vs[0][vr][vc] = *(const float4*)Vg;
    }
    __syncthreads();

    const int nkt = (qt + 1) * 8;
    for (int kt = 0; kt < nkt; kt++) {
        const int buf = kt & 1;
        if (kt + 1 < nkt) {
            const int nb = buf ^ 1;
            const float* a0 = Ag + (kt + 1) * 16;
            float4 v0 = *(const float4*)a0;
            float4 v1 = *(const float4*)(a0 + (size_t)64 * SEQ);
            As[nb][ac+0][ar] = v0.x; As[nb][ac+1][ar] = v0.y;
            As[nb][ac+2][ar] = v0.z; As[nb][ac+3][ar] = v0.w;
            As[nb][ac+0][ar+64] = v1.x; As[nb][ac+1][ar+64] = v1.y;
            As[nb][ac+2][ar+64] = v1.z; As[nb][ac+3][ar+64] = v1.w;
            *(float4*)&Vs[nb][vr][vc] = *(const float4*)(Vg + (size_t)(kt + 1) * vstride);
        }
        #pragma unroll
        for (int ks = 0; ks < 2; ks++) {
            const int k0 = ks * 8;
            unsigned ah[2][4], al[2][4], bh2[4][2], bl2[4][2];
            #pragma unroll
            for (int mi = 0; mi < 2; mi++) {
                const int m0 = wm * 32 + mi * 16;
                split_tf32(As[buf][k0+tg  ][m0+g  ], ah[mi][0], al[mi][0]);
                split_tf32(As[buf][k0+tg  ][m0+g+8], ah[mi][1], al[mi][1]);
                split_tf32(As[buf][k0+tg+4][m0+g  ], ah[mi][2], al[mi][2]);
                split_tf32(As[buf][k0+tg+4][m0+g+8], ah[mi][3], al[mi][3]);
            }
            #pragma unroll
            for (int ni = 0; ni < 4; ni++) {
                const int n0 = wn * 32 + ni * 8;
                split_tf32(Vs[buf][k0+tg  ][n0+g], bh2[ni][0], bl2[ni][0]);
                split_tf32(Vs[buf][k0+tg+4][n0+g], bh2[ni][1], bl2[ni][1]);
            }
            #pragma unroll
            for (int mi = 0; mi < 2; mi++)
                #pragma unroll
                for (int ni = 0; ni < 4; ni++) {
                    mma_tf32(acc[mi][ni], ah[mi], bh2[ni]);
                    mma_tf32(acc[mi][ni], ah[mi], bl2[ni]);
                    mma_tf32(acc[mi][ni], al[mi], bh2[ni]);
                }
        }
        __syncthreads();
    }

    #pragma unroll
    for (int mi = 0; mi < 2; mi++) {
        #pragma unroll
        for (int p = 0; p < 2; p++) {
            const size_t r = (size_t)(b * SEQ + qt * 128 + wm * 32 + mi * 16 + g + p * 8);
            #pragma unroll
            for (int ni = 0; ni < 4; ni++) {
                const int col = h * HD + wn * 32 + ni * 8 + 2 * tg;
                *(float2*)(y + r * CH + col) =
                    make_float2(acc[mi][ni][2*p+0], acc[mi][ni][2*p+1]);
            }
        }
    }
}

// ---------------- host launcher ----------------------------------------------
extern "C" void kernel_launch(void* const* d_in, const int* in_sizes, int n_in,
                              void* d_out, int out_size)
{
    const float* x     = (const float*)d_in[0];
    const float* ln1g  = (const float*)d_in[1];
    const float* ln1b  = (const float*)d_in[2];
    const float* attw  = (const float*)d_in[3];
    const float* attb  = (const float*)d_in[4];
    const float* projw = (const float*)d_in[5];
    const float* projb = (const float*)d_in[6];
    const float* ln2g  = (const float*)d_in[7];
    const float* ln2b  = (const float*)d_in[8];
    const float* fcw   = (const float*)d_in[9];
    const float* fcb   = (const float*)d_in[10];
    const float* fc2w  = (const float*)d_in[11];
    const float* fc2b  = (const float*)d_in[12];
    const float* lnfg  = (const float*)d_in[13];
    const float* lnfb  = (const float*)d_in[14];

    float *px, *pln, *pqkv, *patt, *py, *pfc;
    cudaGetSymbolAddress((void**)&px,   g_x);
    cudaGetSymbolAddress((void**)&pln,  g_ln);
    cudaGetSymbolAddress((void**)&pqkv, g_qkv);
    cudaGetSymbolAddress((void**)&patt, g_att);
    cudaGetSymbolAddress((void**)&py,   g_y);
    cudaGetSymbolAddress((void**)&pfc,  g_fc);

    copy_k<<<(MROWS * CH + 255) / 256, 256>>>(x, px, MROWS * CH);

    for (int l = 0; l < NLAYER; l++) {
        ln_k<<<MROWS, 256>>>(px, ln1g + l * CH, ln1b + l * CH, pln);
        gemm3t<false, false><<<dim3(3 * CH / 128, MROWS / 128), 256>>>(
            pln, attw + (size_t)l * CH * 3 * CH, attb + (size_t)l * 3 * CH,
            nullptr, pqkv, 3 * CH, CH);
        attn_scores_tc<<<dim3(SEQ / 128, SEQ / 128, BATCH * NH), 256>>>(pqkv, patt);
        softmax_k<<<BATCH * NH * SEQ, 128>>>(patt);
        attn_v_tc<<<dim3(SEQ / 128, BATCH * NH), 256>>>(patt, pqkv, py);
        gemm3t<false, true><<<dim3(CH / 128, MROWS / 128), 256>>>(
            py, projw + (size_t)l * CH * CH, projb + (size_t)l * CH,
            px, px, CH, CH);
        ln_k<<<MROWS, 256>>>(px, ln2g + l * CH, ln2b + l * CH, pln);
        gemm3t<true, false><<<dim3(4 * CH / 128, MROWS / 128), 256>>>(
            pln, fcw + (size_t)l * CH * 4 * CH, fcb + (size_t)l * 4 * CH,
            nullptr, pfc, 4 * CH, CH);
        gemm3t<false, true><<<dim3(CH / 128, MROWS / 128), 256>>>(
            pfc, fc2w + (size_t)l * 4 * CH * CH, fc2b + (size_t)l * CH,
            px, px, CH, 4 * CH);
    }
    ln_k<<<MROWS, 256>>>(px, lnfg, lnfb, (float*)d_out);
}

// round 5
// speedup vs baseline: 1.9670x; 1.6809x over previous
#include <cuda_runtime.h>
#include <math.h>

#define NLAYER 12
#define BATCH  4
#define SEQ    1024
#define CH     1024
#define NH     16
#define HD     64
#define MROWS  (BATCH*SEQ)   // 4096
#define LNEPS  1e-5f
#define PIT    20            // smem word pitch: conflict-free fragment reads

// ---------------- scratch (static device memory; no allocs allowed) ----------
__device__ float    g_x[MROWS*CH];                        // residual stream fp32
__device__ unsigned g_lns[MROWS*CH];                      // LN out, split words
__device__ unsigned g_qkvs[(size_t)MROWS*3*CH];           // qkv split words
__device__ unsigned g_att[(size_t)BATCH*NH*SEQ*SEQ];      // att split words (256MB)
__device__ unsigned g_vT[(size_t)BATCH*CH*SEQ];           // V transposed split words
__device__ unsigned g_y[MROWS*CH];                        // attn out split words
__device__ unsigned g_fc[(size_t)MROWS*4*CH];             // mlp hidden split words
// pre-split+transposed weights: WT[n][k] packed words
__device__ unsigned g_attwT[(size_t)NLAYER*3*CH*CH];
__device__ unsigned g_projwT[(size_t)NLAYER*CH*CH];
__device__ unsigned g_fcwT[(size_t)NLAYER*4*CH*CH];
__device__ unsigned g_fc2wT[(size_t)NLAYER*4*CH*CH];

// ---------------- split/merge helpers ----------------------------------------
// word = bf16(v) in low half, bf16(v - hi) in high half
__device__ __forceinline__ unsigned splitw(float v) {
    unsigned u = __float_as_uint(v);
    unsigned hi = (u + 0x7fffu + ((u >> 16) & 1u)) >> 16;       // bf16 rn
    float hf = __uint_as_float(hi << 16);
    unsigned ul = __float_as_uint(v - hf);
    unsigned lo = (ul + 0x7fffu + ((ul >> 16) & 1u)) >> 16;
    return hi | (lo << 16);
}
__device__ __forceinline__ float unsplitw(unsigned w) {
    return __uint_as_float(w << 16) + __uint_as_float(w & 0xffff0000u);
}
__device__ __forceinline__ void mma_bf16(float* c, const unsigned* a, const unsigned* b) {
    asm volatile("mma.sync.aligned.m16n8k16.row.col.f32.bf16.bf16.f32 "
        "{%0,%1,%2,%3}, {%4,%5,%6,%7}, {%8,%9}, {%0,%1,%2,%3};\n"
        : "+f"(c[0]), "+f"(c[1]), "+f"(c[2]), "+f"(c[3])
        : "r"(a[0]), "r"(a[1]), "r"(a[2]), "r"(a[3]), "r"(b[0]), "r"(b[1]));
}
__device__ __forceinline__ float gelu1(float v) {
    const float kk = 0.7978845608028654f;
    return 0.5f * v * (1.f + tanhf(kk * (v + 0.044715f * v * v * v)));
}

// ---------------- simple copy ------------------------------------------------
__global__ void copy_k(const float* __restrict__ in, float* __restrict__ out, int n) {
    int i = blockIdx.x * blockDim.x + threadIdx.x;
    if (i < n) out[i] = in[i];
}

// ---------------- weight split + transpose:  W[K][N] f32 -> WT[N][K] words ---
__global__ void wsplit_k(const float* __restrict__ W, unsigned* __restrict__ WT,
                         int K, int N) {
    __shared__ unsigned sm[32][33];
    const int l = blockIdx.z;
    const float* Wl = W + (size_t)l * K * N;
    unsigned* WTl = WT + (size_t)l * K * N;
    const int k0 = blockIdx.x * 32, n0 = blockIdx.y * 32;
    const int tx = threadIdx.x, ty = threadIdx.y;   // 32 x 8
    #pragma unroll
    for (int i = 0; i < 4; i++)
        sm[ty + 8*i][tx] = splitw(Wl[(size_t)(k0 + ty + 8*i) * N + n0 + tx]);
    __syncthreads();
    #pragma unroll
    for (int i = 0; i < 4; i++)
        WTl[(size_t)(n0 + ty + 8*i) * K + k0 + tx] = sm[tx][ty + 8*i];
}

// ---------------- V transpose: qkv split words -> vT[b*CH + c][seq] ----------
__global__ void vt_k(const unsigned* __restrict__ qkvs, unsigned* __restrict__ vT) {
    __shared__ unsigned sm[32][33];
    const int b = blockIdx.z;
    const int s0 = blockIdx.x * 32, c0 = blockIdx.y * 32;
    const int tx = threadIdx.x, ty = threadIdx.y;   // 32 x 8
    #pragma unroll
    for (int i = 0; i < 4; i++)
        sm[ty + 8*i][tx] = qkvs[(size_t)(b * SEQ + s0 + ty + 8*i) * (3*CH) + 2*CH + c0 + tx];
    __syncthreads();
    #pragma unroll
    for (int i = 0; i < 4; i++)
        vT[(size_t)(b * CH + c0 + ty + 8*i) * SEQ + s0 + tx] = sm[tx][ty + 8*i];
}

// ---------------- layernorm (optionally emits split words) -------------------
template<bool SPLIT>
__global__ void ln_k(const float* __restrict__ in, const float* __restrict__ gam,
                     const float* __restrict__ bet, void* __restrict__ outv) {
    int row = blockIdx.x;
    const float* p = in + (size_t)row * CH;
    float s = 0.f, s2 = 0.f;
    for (int c = threadIdx.x; c < CH; c += blockDim.x) {
        float v = p[c];
        s += v; s2 += v * v;
    }
    __shared__ float sh[16];
    #pragma unroll
    for (int o = 16; o > 0; o >>= 1) {
        s  += __shfl_down_sync(0xffffffffu, s, o);
        s2 += __shfl_down_sync(0xffffffffu, s2, o);
    }
    int lane = threadIdx.x & 31, w = threadIdx.x >> 5;
    if (lane == 0) { sh[w] = s; sh[8 + w] = s2; }
    __syncthreads();
    if (threadIdx.x == 0) {
        float a = 0.f, b = 0.f;
        #pragma unroll
        for (int i = 0; i < 8; i++) { a += sh[i]; b += sh[8 + i]; }
        sh[0] = a; sh[8] = b;
    }
    __syncthreads();
    float mean = sh[0] * (1.f / CH);
    float var  = sh[8] * (1.f / CH) - mean * mean;
    float rstd = rsqrtf(var + LNEPS);
    for (int c = threadIdx.x; c < CH; c += blockDim.x) {
        float v = (p[c] - mean) * rstd * gam[c] + bet[c];
        if (SPLIT) ((unsigned*)outv)[(size_t)row * CH + c] = splitw(v);
        else       ((float*)outv)[(size_t)row * CH + c] = v;
    }
}

// ---------------- bf16 compensated GEMM --------------------------------------
// C = A @ B (+bias)(+GELU)(+Res).  A: [M][K] split words, Bt: [N][K] split
// words.  Per chunk: mma(A,(bh,bh)) + mma(A,(bl,0)) = ahi*bhi+alo*bhi+ahi*blo.
template<bool DO_GELU, bool DO_RES, bool OUT_SPLIT>
__global__ void __launch_bounds__(256, 2) gemmbf(
    const unsigned* __restrict__ A, const unsigned* __restrict__ Bt,
    const float* __restrict__ bias, const float* __restrict__ Res,
    void* __restrict__ Cv, int N, int K)
{
    __shared__ unsigned As[2][128][PIT];
    __shared__ unsigned Bs[2][128][PIT];
    const int tid = threadIdx.x;
    const int row0 = blockIdx.y * 128, col0 = blockIdx.x * 128;
    const int warp = tid >> 5, lane = tid & 31;
    const int wm = warp >> 2, wn = warp & 3;
    const int g = lane >> 2, tg = lane & 3;
    const int lr = tid >> 2, lq = (tid & 3) << 2;

    float acc[4][4][4] = {};

    {   // prologue
        *(uint4*)&As[0][lr][lq]      = *(const uint4*)(A  + (size_t)(row0+lr)*K + lq);
        *(uint4*)&As[0][lr+64][lq]   = *(const uint4*)(A  + (size_t)(row0+lr+64)*K + lq);
        *(uint4*)&Bs[0][lr][lq]      = *(const uint4*)(Bt + (size_t)(col0+lr)*K + lq);
        *(uint4*)&Bs[0][lr+64][lq]   = *(const uint4*)(Bt + (size_t)(col0+lr+64)*K + lq);
    }
    __syncthreads();

    const int nk = K >> 4;
    for (int kt = 0; kt < nk; kt++) {
        const int buf = kt & 1;
        if (kt + 1 < nk) {
            const int nb = buf ^ 1, kw = (kt + 1) << 4;
            *(uint4*)&As[nb][lr][lq]    = *(const uint4*)(A  + (size_t)(row0+lr)*K + kw + lq);
            *(uint4*)&As[nb][lr+64][lq] = *(const uint4*)(A  + (size_t)(row0+lr+64)*K + kw + lq);
            *(uint4*)&Bs[nb][lr][lq]    = *(const uint4*)(Bt + (size_t)(col0+lr)*K + kw + lq);
            *(uint4*)&Bs[nb][lr+64][lq] = *(const uint4*)(Bt + (size_t)(col0+lr+64)*K + kw + lq);
        }
        #pragma unroll
        for (int c = 0; c < 2; c++) {
            const int cw = c * 8;
            unsigned af[4][4], bd[4][2], bl[4][2];
            #pragma unroll
            for (int mi = 0; mi < 4; mi++) {
                const int m0 = wm * 64 + mi * 16;
                af[mi][0] = As[buf][m0+g  ][cw+tg];
                af[mi][1] = As[buf][m0+g+8][cw+tg];
                af[mi][2] = As[buf][m0+g  ][cw+tg+4];
                af[mi][3] = As[buf][m0+g+8][cw+tg+4];
            }
            #pragma unroll
            for (int ni = 0; ni < 4; ni++) {
                const int n0 = wn * 32 + ni * 8;
                unsigned w0 = Bs[buf][n0+g][cw+tg];
                unsigned w1 = Bs[buf][n0+g][cw+tg+4];
                bd[ni][0] = __byte_perm(w0, w0, 0x1010);
                bd[ni][1] = __byte_perm(w1, w1, 0x1010);
                bl[ni][0] = w0 >> 16;
                bl[ni][1] = w1 >> 16;
            }
            #pragma unroll
            for (int mi = 0; mi < 4; mi++)
                #pragma unroll
                for (int ni = 0; ni < 4; ni++) {
                    mma_bf16(acc[mi][ni], af[mi], bd[ni]);
                    mma_bf16(acc[mi][ni], af[mi], bl[ni]);
                }
        }
        __syncthreads();
    }

    // epilogue
    #pragma unroll
    for (int mi = 0; mi < 4; mi++) {
        #pragma unroll
        for (int p = 0; p < 2; p++) {
            const size_t r = (size_t)(row0 + wm * 64 + mi * 16 + g + p * 8);
            #pragma unroll
            for (int ni = 0; ni < 4; ni++) {
                const int col = col0 + wn * 32 + ni * 8 + 2 * tg;
                float2 bv = *(const float2*)(bias + col);
                float v0 = acc[mi][ni][2*p+0] + bv.x;
                float v1 = acc[mi][ni][2*p+1] + bv.y;
                if (DO_GELU) { v0 = gelu1(v0); v1 = gelu1(v1); }
                if (DO_RES) {
                    float2 rv = *(const float2*)(Res + r * N + col);
                    v0 += rv.x; v1 += rv.y;
                }
                if (OUT_SPLIT)
                    *(uint2*)((unsigned*)Cv + r * N + col) =
                        make_uint2(splitw(v0), splitw(v1));
                else
                    *(float2*)((float*)Cv + r * N + col) = make_float2(v0, v1);
            }
        }
    }
}

// ---------------- attention scores (compensated bf16, causal tile skip) ------
__global__ void __launch_bounds__(256, 2) attn_scores_bf(
    const unsigned* __restrict__ qkvs, unsigned* __restrict__ att)
{
    const int bh = blockIdx.z, b = bh >> 4, h = bh & 15;
    const int qt = blockIdx.y, kt = blockIdx.x;
    if (kt > qt) return;

    __shared__ unsigned Qs[2][128][PIT];
    __shared__ unsigned Ks[2][128][PIT];
    const int tid = threadIdx.x;
    const int warp = tid >> 5, lane = tid & 31;
    const int wm = warp >> 2, wn = warp & 3;
    const int g = lane >> 2, tg = lane & 3;
    const int lr = tid >> 2, lq = (tid & 3) << 2;
    const size_t RS = 3 * CH;
    const unsigned* Qb = qkvs + (size_t)(b * SEQ + qt * 128) * RS + h * HD;
    const unsigned* Kb = qkvs + (size_t)(b * SEQ + kt * 128) * RS + CH + h * HD;

    float acc[4][4][4] = {};

    {
        *(uint4*)&Qs[0][lr][lq]    = *(const uint4*)(Qb + (size_t)lr * RS + lq);
        *(uint4*)&Qs[0][lr+64][lq] = *(const uint4*)(Qb + (size_t)(lr+64) * RS + lq);
        *(uint4*)&Ks[0][lr][lq]    = *(const uint4*)(Kb + (size_t)lr * RS + lq);
        *(uint4*)&Ks[0][lr+64][lq] = *(const uint4*)(Kb + (size_t)(lr+64) * RS + lq);
    }
    __syncthreads();

    const int nk = HD >> 4;   // 4 steps of 16 words
    for (int dt = 0; dt < nk; dt++) {
        const int buf = dt & 1;
        if (dt + 1 < nk) {
            const int nb = buf ^ 1, kw = (dt + 1) << 4;
            *(uint4*)&Qs[nb][lr][lq]    = *(const uint4*)(Qb + (size_t)lr * RS + kw + lq);
            *(uint4*)&Qs[nb][lr+64][lq] = *(const uint4*)(Qb + (size_t)(lr+64) * RS + kw + lq);
            *(uint4*)&Ks[nb][lr][lq]    = *(const uint4*)(Kb + (size_t)lr * RS + kw + lq);
            *(uint4*)&Ks[nb][lr+64][lq] = *(const uint4*)(Kb + (size_t)(lr+64) * RS + kw + lq);
        }
        #pragma unroll
        for (int c = 0; c < 2; c++) {
            const int cw = c * 8;
            unsigned af[4][4], bd[4][2], bl[4][2];
            #pragma unroll
            for (int mi = 0; mi < 4; mi++) {
                const int m0 = wm * 64 + mi * 16;
                af[mi][0] = Qs[buf][m0+g  ][cw+tg];
                af[mi][1] = Qs[buf][m0+g+8][cw+tg];
                af[mi][2] = Qs[buf][m0+g  ][cw+tg+4];
                af[mi][3] = Qs[buf][m0+g+8][cw+tg+4];
            }
            #pragma unroll
            for (int ni = 0; ni < 4; ni++) {
                const int n0 = wn * 32 + ni * 8;
                unsigned w0 = Ks[buf][n0+g][cw+tg];
                unsigned w1 = Ks[buf][n0+g][cw+tg+4];
                bd[ni][0] = __byte_perm(w0, w0, 0x1010);
                bd[ni][1] = __byte_perm(w1, w1, 0x1010);
                bl[ni][0] = w0 >> 16;
                bl[ni][1] = w1 >> 16;
            }
            #pragma unroll
            for (int mi = 0; mi < 4; mi++)
                #pragma unroll
                for (int ni = 0; ni < 4; ni++) {
                    mma_bf16(acc[mi][ni], af[mi], bd[ni]);
                    mma_bf16(acc[mi][ni], af[mi], bl[ni]);
                }
        }
        __syncthreads();
    }

    const bool diag = (qt == kt);
    const float scale = 0.125f;   // 1/sqrt(64)
    #pragma unroll
    for (int mi = 0; mi < 4; mi++) {
        #pragma unroll
        for (int p = 0; p < 2; p++) {
            const int q = qt * 128 + wm * 64 + mi * 16 + g + p * 8;
            unsigned* rowp = att + ((size_t)bh * SEQ + q) * SEQ + kt * 128;
            #pragma unroll
            for (int ni = 0; ni < 4; ni++) {
                const int kc = wn * 32 + ni * 8 + 2 * tg;
                unsigned w0 = splitw(acc[mi][ni][2*p+0] * scale);
                unsigned w1 = splitw(acc[mi][ni][2*p+1] * scale);
                if (!diag) {
                    *(uint2*)(rowp + kc) = make_uint2(w0, w1);
                } else {
                    const int kg = kt * 128 + kc;
                    if (kg     <= q) rowp[kc]     = w0;
                    if (kg + 1 <= q) rowp[kc + 1] = w1;
                }
            }
        }
    }
}

// ---------------- causal softmax over split words ----------------------------
__global__ void softmax_w(unsigned* __restrict__ att) {
    const int row = blockIdx.x;
    const int q = row & (SEQ - 1);
    unsigned* p = att + (size_t)row * SEQ;
    const int n = q + 1;
    const int tid = threadIdx.x;

    float m = -1e30f;
    for (int j = tid; j < n; j += blockDim.x) m = fmaxf(m, unsplitw(p[j]));
    __shared__ float shm[4], shs[4];
    #pragma unroll
    for (int o = 16; o > 0; o >>= 1) m = fmaxf(m, __shfl_xor_sync(0xffffffffu, m, o));
    if ((tid & 31) == 0) shm[tid >> 5] = m;
    __syncthreads();
    m = fmaxf(fmaxf(shm[0], shm[1]), fmaxf(shm[2], shm[3]));

    float s = 0.f;
    for (int j = tid; j < n; j += blockDim.x) {
        float e = __expf(unsplitw(p[j]) - m);
        p[j] = splitw(e); s += e;
    }
    #pragma unroll
    for (int o = 16; o > 0; o >>= 1) s += __shfl_xor_sync(0xffffffffu, s, o);
    if ((tid & 31) == 0) shs[tid >> 5] = s;
    __syncthreads();
    s = shs[0] + shs[1] + shs[2] + shs[3];
    float inv = 1.f / s;
    for (int j = tid; j < n; j += blockDim.x) p[j] = splitw(unsplitw(p[j]) * inv);
    for (int j = n + tid; j < SEQ; j += blockDim.x) p[j] = 0u;
}

// ---------------- att @ V (compensated bf16) ---------------------------------
// Block = 128 q x 64 d (one head).  8 warps 4x2, warp 32x32.
__global__ void __launch_bounds__(256, 2) attn_v_bf(
    const unsigned* __restrict__ att, const unsigned* __restrict__ vT,
    unsigned* __restrict__ y)
{
    const int qt = blockIdx.x, bh = blockIdx.y;
    const int b = bh >> 4, h = bh & 15;
    __shared__ unsigned As[2][128][PIT];
    __shared__ unsigned Vs[2][64][PIT];
    const int tid = threadIdx.x;
    const int warp = tid >> 5, lane = tid & 31;
    const int wm = warp >> 1, wn = warp & 1;
    const int g = lane >> 2, tg = lane & 3;
    const int lr = tid >> 2, lq = (tid & 3) << 2;
    const unsigned* Ab = att + (size_t)(bh * SEQ + qt * 128) * SEQ;
    const unsigned* Vb = vT + (size_t)bh * HD * SEQ;

    float acc[2][4][4] = {};

    {
        *(uint4*)&As[0][lr][lq]    = *(const uint4*)(Ab + (size_t)lr * SEQ + lq);
        *(uint4*)&As[0][lr+64][lq] = *(const uint4*)(Ab + (size_t)(lr+64) * SEQ + lq);
        *(uint4*)&Vs[0][lr & 63][lq] = *(const uint4*)(Vb + (size_t)(lr & 63) * SEQ + lq);
    }
    __syncthreads();

    const int nkt = (qt + 1) * 8;
    for (int kt = 0; kt < nkt; kt++) {
        const int buf = kt & 1;
        if (kt + 1 < nkt) {
            const int nb = buf ^ 1, kw = (kt + 1) << 4;
            *(uint4*)&As[nb][lr][lq]    = *(const uint4*)(Ab + (size_t)lr * SEQ + kw + lq);
            *(uint4*)&As[nb][lr+64][lq] = *(const uint4*)(Ab + (size_t)(lr+64) * SEQ + kw + lq);
            if (lr < 64)
                *(uint4*)&Vs[nb][lr][lq] = *(const uint4*)(Vb + (size_t)lr * SEQ + kw + lq);
        }
        #pragma unroll
        for (int c = 0; c < 2; c++) {
            const int cw = c * 8;
            unsigned af[2][4], bd[4][2], bl[4][2];
            #pragma unroll
            for (int mi = 0; mi < 2; mi++) {
                const int m0 = wm * 32 + mi * 16;
                af[mi][0] = As[buf][m0+g  ][cw+tg];
                af[mi][1] = As[buf][m0+g+8][cw+tg];
                af[mi][2] = As[buf][m0+g  ][cw+tg+4];
                af[mi][3] = As[buf][m0+g+8][cw+tg+4];
            }
            #pragma unroll
            for (int ni = 0; ni < 4; ni++) {
                const int n0 = wn * 32 + ni * 8;
                unsigned w0 = Vs[buf][n0+g][cw+tg];
                unsigned w1 = Vs[buf][n0+g][cw+tg+4];
                bd[ni][0] = __byte_perm(w0, w0, 0x1010);
                bd[ni][1] = __byte_perm(w1, w1, 0x1010);
                bl[ni][0] = w0 >> 16;
                bl[ni][1] = w1 >> 16;
            }
            #pragma unroll
            for (int mi = 0; mi < 2; mi++)
                #pragma unroll
                for (int ni = 0; ni < 4; ni++) {
                    mma_bf16(acc[mi][ni], af[mi], bd[ni]);
                    mma_bf16(acc[mi][ni], af[mi], bl[ni]);
                }
        }
        __syncthreads();
    }

    #pragma unroll
    for (int mi = 0; mi < 2; mi++) {
        #pragma unroll
        for (int p = 0; p < 2; p++) {
            const size_t r = (size_t)(b * SEQ + qt * 128 + wm * 32 + mi * 16 + g + p * 8);
            #pragma unroll
            for (int ni = 0; ni < 4; ni++) {
                const int col = h * HD + wn * 32 + ni * 8 + 2 * tg;
                *(uint2*)(y + r * CH + col) =
                    make_uint2(splitw(acc[mi][ni][2*p+0]), splitw(acc[mi][ni][2*p+1]));
            }
        }
    }
}

// ---------------- host launcher ----------------------------------------------
extern "C" void kernel_launch(void* const* d_in, const int* in_sizes, int n_in,
                              void* d_out, int out_size)
{
    const float* x     = (const float*)d_in[0];
    const float* ln1g  = (const float*)d_in[1];
    const float* ln1b  = (const float*)d_in[2];
    const float* attw  = (const float*)d_in[3];
    const float* attb  = (const float*)d_in[4];
    const float* projw = (const float*)d_in[5];
    const float* projb = (const float*)d_in[6];
    const float* ln2g  = (const float*)d_in[7];
    const float* ln2b  = (const float*)d_in[8];
    const float* fcw   = (const float*)d_in[9];
    const float* fcb   = (const float*)d_in[10];
    const float* fc2w  = (const float*)d_in[11];
    const float* fc2b  = (const float*)d_in[12];
    const float* lnfg  = (const float*)d_in[13];
    const float* lnfb  = (const float*)d_in[14];

    float *px;
    unsigned *plns, *pqkvs, *patt, *pvT, *py, *pfc;
    unsigned *pattwT, *pprojwT, *pfcwT, *pfc2wT;
    cudaGetSymbolAddress((void**)&px,      g_x);
    cudaGetSymbolAddress((void**)&plns,    g_lns);
    cudaGetSymbolAddress((void**)&pqkvs,   g_qkvs);
    cudaGetSymbolAddress((void**)&patt,    g_att);
    cudaGetSymbolAddress((void**)&pvT,     g_vT);
    cudaGetSymbolAddress((void**)&py,      g_y);
    cudaGetSymbolAddress((void**)&pfc,     g_fc);
    cudaGetSymbolAddress((void**)&pattwT,  g_attwT);
    cudaGetSymbolAddress((void**)&pprojwT, g_projwT);
    cudaGetSymbolAddress((void**)&pfcwT,   g_fcwT);
    cudaGetSymbolAddress((void**)&pfc2wT,  g_fc2wT);

    const dim3 t32x8(32, 8);
    // one-time weight split+transpose (per launch; deterministic)
    wsplit_k<<<dim3(CH/32, 3*CH/32, NLAYER), t32x8>>>(attw,  pattwT,  CH,   3*CH);
    wsplit_k<<<dim3(CH/32,   CH/32, NLAYER), t32x8>>>(projw, pprojwT, CH,   CH);
    wsplit_k<<<dim3(CH/32, 4*CH/32, NLAYER), t32x8>>>(fcw,   pfcwT,   CH,   4*CH);
    wsplit_k<<<dim3(4*CH/32, CH/32, NLAYER), t32x8>>>(fc2w,  pfc2wT,  4*CH, CH);

    copy_k<<<(MROWS * CH + 255) / 256, 256>>>(x, px, MROWS * CH);

    for (int l = 0; l < NLAYER; l++) {
        ln_k<true><<<MROWS, 256>>>(px, ln1g + l * CH, ln1b + l * CH, plns);
        gemmbf<false, false, true><<<dim3(3 * CH / 128, MROWS / 128), 256>>>(
            plns, pattwT + (size_t)l * 3 * CH * CH, attb + (size_t)l * 3 * CH,
            nullptr, pqkvs, 3 * CH, CH);
        vt_k<<<dim3(SEQ/32, CH/32, BATCH), t32x8>>>(pqkvs, pvT);
        attn_scores_bf<<<dim3(SEQ/128, SEQ/128, BATCH * NH), 256>>>(pqkvs, patt);
        softmax_w<<<BATCH * NH * SEQ, 128>>>(patt);
        attn_v_bf<<<dim3(SEQ/128, BATCH * NH), 256>>>(patt, pvT, py);
        gemmbf<false, true, false><<<dim3(CH / 128, MROWS / 128), 256>>>(
            py, pprojwT + (size_t)l * CH * CH, projb + (size_t)l * CH,
            px, px, CH, CH);
        ln_k<true><<<MROWS, 256>>>(px, ln2g + l * CH, ln2b + l * CH, plns);
        gemmbf<true, false, true><<<dim3(4 * CH / 128, MROWS / 128), 256>>>(
            plns, pfcwT + (size_t)l * 4 * CH * CH, fcb + (size_t)l * 4 * CH,
            nullptr, pfc, 4 * CH, CH);
        gemmbf<false, true, false><<<dim3(CH / 128, MROWS / 128), 256>>>(
            pfc, pfc2wT + (size_t)l * 4 * CH * CH, fc2b + (size_t)l * CH,
            px, px, CH, 4 * CH);
    }
    ln_k<false><<<MROWS, 256>>>(px, lnfg, lnfb, (float*)d_out);
}

// round 9
// speedup vs baseline: 2.0149x; 1.0244x over previous
#include <cuda_runtime.h>
#include <math.h>
#include <stdint.h>

#define NLAYER 12
#define BATCH  4
#define SEQ    1024
#define CH     1024
#define NH     16
#define HD     64
#define MROWS  (BATCH*SEQ)   // 4096
#define LNEPS  1e-5f
#define PIT    20            // attention smem word pitch (16B-aligned rows, conflict-free ldsm)
#define GP     36            // gemm smem word pitch (144B rows, conflict-free ldsm)
#define BKW    32            // gemm k-chunk in words (= 64 k' bf16)

// ---------------- scratch (static device memory; no allocs allowed) ----------
__device__ float    g_x[MROWS*CH];
__device__ unsigned g_lns[MROWS*CH];                      // LN out, packed (hi,lo)
__device__ unsigned g_qkvs[(size_t)MROWS*3*CH];
__device__ unsigned g_att[(size_t)BATCH*NH*SEQ*SEQ];
__device__ unsigned g_vT[(size_t)BATCH*CH*SEQ];
__device__ unsigned g_y[MROWS*CH];
__device__ unsigned g_fc[(size_t)MROWS*4*CH];
// pre-split+transposed weights: WT[n][k] packed words
__device__ unsigned g_attwT[(size_t)NLAYER*3*CH*CH];
__device__ unsigned g_projwT[(size_t)NLAYER*CH*CH];
__device__ unsigned g_fcwT[(size_t)NLAYER*4*CH*CH];
__device__ unsigned g_fc2wT[(size_t)NLAYER*4*CH*CH];

// ---------------- helpers -----------------------------------------------------
__device__ __forceinline__ unsigned splitw(float v) {          // hi | lo<<16
    unsigned u = __float_as_uint(v);
    unsigned hi = (u + 0x7fffu + ((u >> 16) & 1u)) >> 16;
    float hf = __uint_as_float(hi << 16);
    unsigned ul = __float_as_uint(v - hf);
    unsigned lo = (ul + 0x7fffu + ((ul >> 16) & 1u)) >> 16;
    return hi | (lo << 16);
}
__device__ __forceinline__ float unsplitw(unsigned w) {
    return __uint_as_float(w << 16) + __uint_as_float(w & 0xffff0000u);
}
__device__ __forceinline__ void mma_bf16(float* c, const unsigned* a, const unsigned* b) {
    asm volatile("mma.sync.aligned.m16n8k16.row.col.f32.bf16.bf16.f32 "
        "{%0,%1,%2,%3}, {%4,%5,%6,%7}, {%8,%9}, {%0,%1,%2,%3};\n"
        : "+f"(c[0]), "+f"(c[1]), "+f"(c[2]), "+f"(c[3])
        : "r"(a[0]), "r"(a[1]), "r"(a[2]), "r"(a[3]), "r"(b[0]), "r"(b[1]));
}
__device__ __forceinline__ float gelu1(float v) {
    const float kk = 0.7978845608028654f;
    return 0.5f * v * (1.f + tanhf(kk * (v + 0.044715f * v * v * v)));
}
__device__ __forceinline__ uint32_t smaddr(const void* p) {
    uint32_t u;
    asm("{ .reg .u64 t; cvta.to.shared.u64 t, %1; cvt.u32.u64 %0, t; }" : "=r"(u) : "l"(p));
    return u;
}
__device__ __forceinline__ void ldsm4(unsigned& r0, unsigned& r1, unsigned& r2,
                                      unsigned& r3, uint32_t a) {
    asm volatile("ldmatrix.sync.aligned.m8n8.x4.shared.b16 {%0,%1,%2,%3}, [%4];"
                 : "=r"(r0), "=r"(r1), "=r"(r2), "=r"(r3) : "r"(a));
}
__device__ __forceinline__ void ldsm2(unsigned& r0, unsigned& r1, uint32_t a) {
    asm volatile("ldmatrix.sync.aligned.m8n8.x2.shared.b16 {%0,%1}, [%2];"
                 : "=r"(r0), "=r"(r1) : "r"(a));
}
__device__ __forceinline__ void cpa16(uint32_t dst, const void* src) {
    asm volatile("cp.async.cg.shared.global [%0], [%1], 16;" :: "r"(dst), "l"(src));
}
__device__ __forceinline__ void cpcommit() { asm volatile("cp.async.commit_group;"); }
template<int N> __device__ __forceinline__ void cpwait() {
    asm volatile("cp.async.wait_group %0;" :: "n"(N));
}

// ---------------- simple copy ------------------------------------------------
__global__ void copy_k(const float* __restrict__ in, float* __restrict__ out, int n) {
    int i = blockIdx.x * blockDim.x + threadIdx.x;
    if (i < n) out[i] = in[i];
}

// ---------------- weight split + transpose:  W[K][N] f32 -> WT[N][K] words ---
__global__ void wsplit_k(const float* __restrict__ W, unsigned* __restrict__ WT,
                         int K, int N) {
    __shared__ unsigned sm[32][33];
    const int l = blockIdx.z;
    const float* Wl = W + (size_t)l * K * N;
    unsigned* WTl = WT + (size_t)l * K * N;
    const int k0 = blockIdx.x * 32, n0 = blockIdx.y * 32;
    const int tx = threadIdx.x, ty = threadIdx.y;
    #pragma unroll
    for (int i = 0; i < 4; i++)
        sm[ty + 8*i][tx] = splitw(Wl[(size_t)(k0 + ty + 8*i) * N + n0 + tx]);
    __syncthreads();
    #pragma unroll
    for (int i = 0; i < 4; i++)
        WTl[(size_t)(n0 + ty + 8*i) * K + k0 + tx] = sm[tx][ty + 8*i];
}

// ---------------- V transpose ------------------------------------------------
__global__ void vt_k(const unsigned* __restrict__ qkvs, unsigned* __restrict__ vT) {
    __shared__ unsigned sm[32][33];
    const int b = blockIdx.z;
    const int s0 = blockIdx.x * 32, c0 = blockIdx.y * 32;
    const int tx = threadIdx.x, ty = threadIdx.y;
    #pragma unroll
    for (int i = 0; i < 4; i++)
        sm[ty + 8*i][tx] = qkvs[(size_t)(b * SEQ + s0 + ty + 8*i) * (3*CH) + 2*CH + c0 + tx];
    __syncthreads();
    #pragma unroll
    for (int i = 0; i < 4; i++)
        vT[(size_t)(b * CH + c0 + ty + 8*i) * SEQ + s0 + tx] = sm[tx][ty + 8*i];
}

// ---------------- layernorm --------------------------------------------------
template<bool SPLIT>
__global__ void ln_k(const float* __restrict__ in, const float* __restrict__ gam,
                     const float* __restrict__ bet, void* __restrict__ outv) {
    int row = blockIdx.x;
    const float* p = in + (size_t)row * CH;
    float s = 0.f, s2 = 0.f;
    for (int c = threadIdx.x; c < CH; c += blockDim.x) {
        float v = p[c];
        s += v; s2 += v * v;
    }
    __shared__ float sh[16];
    #pragma unroll
    for (int o = 16; o > 0; o >>= 1) {
        s  += __shfl_down_sync(0xffffffffu, s, o);
        s2 += __shfl_down_sync(0xffffffffu, s2, o);
    }
    int lane = threadIdx.x & 31, w = threadIdx.x >> 5;
    if (lane == 0) { sh[w] = s; sh[8 + w] = s2; }
    __syncthreads();
    if (threadIdx.x == 0) {
        float a = 0.f, b = 0.f;
        #pragma unroll
        for (int i = 0; i < 8; i++) { a += sh[i]; b += sh[8 + i]; }
        sh[0] = a; sh[8] = b;
    }
    __syncthreads();
    float mean = sh[0] * (1.f / CH);
    float var  = sh[8] * (1.f / CH) - mean * mean;
    float rstd = rsqrtf(var + LNEPS);
    for (int c = threadIdx.x; c < CH; c += blockDim.x) {
        float v = (p[c] - mean) * rstd * gam[c] + bet[c];
        if (SPLIT) ((unsigned*)outv)[(size_t)row * CH + c] = splitw(v);
        else       ((float*)outv)[(size_t)row * CH + c] = v;
    }
}

// ---------------- bf16 compensated GEMM (cp.async + ldmatrix) ----------------
// C = A @ B (+bias)(+GELU)(+Res).  A: [M][K] packed words; Bt: [N][K] packed.
// 128x128 CTA tile, BKW=32 words/stage, 2-stage cp.async, 8 warps 2x4.
#define GSMEM (2*128*GP*4*2)   // 73728 B

template<bool DO_GELU, bool DO_RES, bool OUT_SPLIT>
__global__ void __launch_bounds__(256, 2) gemmbf(
    const unsigned* __restrict__ A, const unsigned* __restrict__ Bt,
    const float* __restrict__ bias, const float* __restrict__ Res,
    void* __restrict__ Cv, int N, int K)
{
    extern __shared__ unsigned sm[];
    unsigned* As = sm;                 // [2][128][GP]
    unsigned* Bs = sm + 2 * 128 * GP;
    const int tid = threadIdx.x;
    const int row0 = blockIdx.y * 128, col0 = blockIdx.x * 128;
    const int warp = tid >> 5, lane = tid & 31;
    const int wm = warp >> 2, wn = warp & 3;
    const int g = lane >> 2, tg = lane & 3;
    const int ldr = tid >> 3, ldc = (tid & 7) << 2;   // 32 rows x 8 chunks per pass

    float acc[4][4][4] = {};

    // ldmatrix source addresses (per-lane, fixed row/col-group)
    const int arow = lane & 15, asel = (lane >> 4) << 2;
    const int brow = lane & 7,  bsel = ((lane >> 3) & 1) << 2;

    auto load_stage = [&](int s, int kw) {
        unsigned* Ad = As + s * 128 * GP;
        unsigned* Bd = Bs + s * 128 * GP;
        #pragma unroll
        for (int j = 0; j < 4; j++) {
            int r = ldr + j * 32;
            cpa16(smaddr(Ad + r * GP + ldc), A  + (size_t)(row0 + r) * K + kw + ldc);
        }
        #pragma unroll
        for (int j = 0; j < 4; j++) {
            int r = ldr + j * 32;
            cpa16(smaddr(Bd + r * GP + ldc), Bt + (size_t)(col0 + r) * K + kw + ldc);
        }
        cpcommit();
    };

    load_stage(0, 0);
    load_stage(1, BKW);

    const int nk = K >> 5;
    for (int kt = 0; kt < nk; kt++) {
        const int s = kt & 1;
        cpwait<1>();
        __syncthreads();
        const unsigned* Ab = As + s * 128 * GP;
        const unsigned* Bb = Bs + s * 128 * GP;
        #pragma unroll
        for (int c = 0; c < 4; c++) {
            const int cw = c * 8;
            unsigned af[4][4];
            #pragma unroll
            for (int mi = 0; mi < 4; mi++) {
                const int m0 = wm * 64 + mi * 16;
                ldsm4(af[mi][0], af[mi][1], af[mi][2], af[mi][3],
                      smaddr(Ab + (m0 + arow) * GP + cw + asel));
            }
            #pragma unroll
            for (int ni = 0; ni < 4; ni++) {
                const int n0 = wn * 32 + ni * 8;
                unsigned w0, w1;
                ldsm2(w0, w1, smaddr(Bb + (n0 + brow) * GP + cw + bsel));
                unsigned bd[2], bl[2];
                bd[0] = __byte_perm(w0, w0, 0x1010);
                bd[1] = __byte_perm(w1, w1, 0x1010);
                bl[0] = w0 >> 16;
                bl[1] = w1 >> 16;
                #pragma unroll
                for (int mi = 0; mi < 4; mi++) {
                    mma_bf16(acc[mi][ni], af[mi], bd);
                    mma_bf16(acc[mi][ni], af[mi], bl);
                }
            }
        }
        __syncthreads();
        if (kt + 2 < nk) load_stage(s, (kt + 2) * BKW);
    }

    // epilogue
    #pragma unroll
    for (int mi = 0; mi < 4; mi++) {
        #pragma unroll
        for (int p = 0; p < 2; p++) {
            const size_t r = (size_t)(row0 + wm * 64 + mi * 16 + g + p * 8);
            #pragma unroll
            for (int ni = 0; ni < 4; ni++) {
                const int col = col0 + wn * 32 + ni * 8 + 2 * tg;
                float2 bv = *(const float2*)(bias + col);
                float v0 = acc[mi][ni][2*p+0] + bv.x;
                float v1 = acc[mi][ni][2*p+1] + bv.y;
                if (DO_GELU) { v0 = gelu1(v0); v1 = gelu1(v1); }
                if (DO_RES) {
                    float2 rv = *(const float2*)(Res + r * N + col);
                    v0 += rv.x; v1 += rv.y;
                }
                if (OUT_SPLIT)
                    *(uint2*)((unsigned*)Cv + r * N + col) =
                        make_uint2(splitw(v0), splitw(v1));
                else
                    *(float2*)((float*)Cv + r * N + col) = make_float2(v0, v1);
            }
        }
    }
}

// ---------------- attention scores (compensated bf16, ldmatrix) --------------
__global__ void __launch_bounds__(256, 2) attn_scores_bf(
    const unsigned* __restrict__ qkvs, unsigned* __restrict__ att)
{
    const int bh = blockIdx.z, b = bh >> 4, h = bh & 15;
    const int qt = blockIdx.y, kt = blockIdx.x;
    if (kt > qt) return;

    __shared__ unsigned Qs[2][128][PIT];
    __shared__ unsigned Ks[2][128][PIT];
    const int tid = threadIdx.x;
    const int warp = tid >> 5, lane = tid & 31;
    const int wm = warp >> 2, wn = warp & 3;
    const int g = lane >> 2, tg = lane & 3;
    const int lr = tid >> 2, lq = (tid & 3) << 2;
    const int arow = lane & 15, asel = (lane >> 4) << 2;
    const int brow = lane & 7,  bsel = ((lane >> 3) & 1) << 2;
    const size_t RS = 3 * CH;
    const unsigned* Qb = qkvs + (size_t)(b * SEQ + qt * 128) * RS + h * HD;
    const unsigned* Kb = qkvs + (size_t)(b * SEQ + kt * 128) * RS + CH + h * HD;

    float acc[4][4][4] = {};
    {
        *(uint4*)&Qs[0][lr][lq]    = *(const uint4*)(Qb + (size_t)lr * RS + lq);
        *(uint4*)&Qs[0][lr+64][lq] = *(const uint4*)(Qb + (size_t)(lr+64) * RS + lq);
        *(uint4*)&Ks[0][lr][lq]    = *(const uint4*)(Kb + (size_t)lr * RS + lq);
        *(uint4*)&Ks[0][lr+64][lq] = *(const uint4*)(Kb + (size_t)(lr+64) * RS + lq);
    }
    __syncthreads();
    const int nk = HD >> 4;
    for (int dt = 0; dt < nk; dt++) {
        const int buf = dt & 1;
        if (dt + 1 < nk) {
            const int nb = buf ^ 1, kw = (dt + 1) << 4;
            *(uint4*)&Qs[nb][lr][lq]    = *(const uint4*)(Qb + (size_t)lr * RS + kw + lq);
            *(uint4*)&Qs[nb][lr+64][lq] = *(const uint4*)(Qb + (size_t)(lr+64) * RS + kw + lq);
            *(uint4*)&Ks[nb][lr][lq]    = *(const uint4*)(Kb + (size_t)lr * RS + kw + lq);
            *(uint4*)&Ks[nb][lr+64][lq] = *(const uint4*)(Kb + (size_t)(lr+64) * RS + kw + lq);
        }
        #pragma unroll
        for (int c = 0; c < 2; c++) {
            const int cw = c * 8;
            unsigned af[4][4];
            #pragma unroll
            for (int mi = 0; mi < 4; mi++) {
                const int m0 = wm * 64 + mi * 16;
                ldsm4(af[mi][0], af[mi][1], af[mi][2], af[mi][3],
                      smaddr(&Qs[buf][m0 + arow][cw + asel]));
            }
            #pragma unroll
            for (int ni = 0; ni < 4; ni++) {
                const int n0 = wn * 32 + ni * 8;
                unsigned w0, w1;
                ldsm2(w0, w1, smaddr(&Ks[buf][n0 + brow][cw + bsel]));
                unsigned bd[2], bl[2];
                bd[0] = __byte_perm(w0, w0, 0x1010);
                bd[1] = __byte_perm(w1, w1, 0x1010);
                bl[0] = w0 >> 16;
                bl[1] = w1 >> 16;
                #pragma unroll
                for (int mi = 0; mi < 4; mi++) {
                    mma_bf16(acc[mi][ni], af[mi], bd);
                    mma_bf16(acc[mi][ni], af[mi], bl);
                }
            }
        }
        __syncthreads();
    }
    const bool diag = (qt == kt);
    const float scale = 0.125f;
    #pragma unroll
    for (int mi = 0; mi < 4; mi++)
        #pragma unroll
        for (int p = 0; p < 2; p++) {
            const int q = qt * 128 + wm * 64 + mi * 16 + g + p * 8;
            unsigned* rowp = att + ((size_t)bh * SEQ + q) * SEQ + kt * 128;
            #pragma unroll
            for (int ni = 0; ni < 4; ni++) {
                const int kc = wn * 32 + ni * 8 + 2 * tg;
                unsigned w0 = splitw(acc[mi][ni][2*p+0] * scale);
                unsigned w1 = splitw(acc[mi][ni][2*p+1] * scale);
                if (!diag) {
                    *(uint2*)(rowp + kc) = make_uint2(w0, w1);
                } else {
                    const int kg = kt * 128 + kc;
                    if (kg     <= q) rowp[kc]     = w0;
                    if (kg + 1 <= q) rowp[kc + 1] = w1;
                }
            }
        }
}

// ---------------- causal softmax over packed words ---------------------------
__global__ void softmax_w(unsigned* __restrict__ att) {
    const int row = blockIdx.x;
    const int q = row & (SEQ - 1);
    unsigned* p = att + (size_t)row * SEQ;
    const int n = q + 1;
    const int tid = threadIdx.x;

    float m = -1e30f;
    for (int j = tid; j < n; j += blockDim.x) m = fmaxf(m, unsplitw(p[j]));
    __shared__ float shm[4], shs[4];
    #pragma unroll
    for (int o = 16; o > 0; o >>= 1) m = fmaxf(m, __shfl_xor_sync(0xffffffffu, m, o));
    if ((tid & 31) == 0) shm[tid >> 5] = m;
    __syncthreads();
    m = fmaxf(fmaxf(shm[0], shm[1]), fmaxf(shm[2], shm[3]));

    float s = 0.f;
    for (int j = tid; j < n; j += blockDim.x) {
        float e = __expf(unsplitw(p[j]) - m);
        p[j] = splitw(e); s += e;
    }
    #pragma unroll
    for (int o = 16; o > 0; o >>= 1) s += __shfl_xor_sync(0xffffffffu, s, o);
    if ((tid & 31) == 0) shs[tid >> 5] = s;
    __syncthreads();
    s = shs[0] + shs[1] + shs[2] + shs[3];
    float inv = 1.f / s;
    for (int j = tid; j < n; j += blockDim.x) p[j] = splitw(unsplitw(p[j]) * inv);
    for (int j = n + tid; j < SEQ; j += blockDim.x) p[j] = 0u;
}

// ---------------- att @ V (compensated bf16, ldmatrix) -----------------------
__global__ void __launch_bounds__(256, 2) attn_v_bf(
    const unsigned* __restrict__ att, const unsigned* __restrict__ vT,
    unsigned* __restrict__ y)
{
    const int qt = blockIdx.x, bh = blockIdx.y;
    const int b = bh >> 4, h = bh & 15;
    __shared__ unsigned As[2][128][PIT];
    __shared__ unsigned Vs[2][64][PIT];
    const int tid = threadIdx.x;
    const int warp = tid >> 5, lane = tid & 31;
    const int wm = warp >> 1, wn = warp & 1;
    const int g = lane >> 2, tg = lane & 3;
    const int lr = tid >> 2, lq = (tid & 3) << 2;
    const int arow = lane & 15, asel = (lane >> 4) << 2;
    const int brow = lane & 7,  bsel = ((lane >> 3) & 1) << 2;
    const unsigned* Ab = att + (size_t)(bh * SEQ + qt * 128) * SEQ;
    const unsigned* Vb = vT + (size_t)bh * HD * SEQ;

    float acc[2][4][4] = {};
    {
        *(uint4*)&As[0][lr][lq]    = *(const uint4*)(Ab + (size_t)lr * SEQ + lq);
        *(uint4*)&As[0][lr+64][lq] = *(const uint4*)(Ab + (size_t)(lr+64) * SEQ + lq);
        *(uint4*)&Vs[0][lr & 63][lq] = *(const uint4*)(Vb + (size_t)(lr & 63) * SEQ + lq);
    }
    __syncthreads();
    const int nkt = (qt + 1) * 8;
    for (int kt = 0; kt < nkt; kt++) {
        const int buf = kt & 1;
        if (kt + 1 < nkt) {
            const int nb = buf ^ 1, kw = (kt + 1) << 4;
            *(uint4*)&As[nb][lr][lq]    = *(const uint4*)(Ab + (size_t)lr * SEQ + kw + lq);
            *(uint4*)&As[nb][lr+64][lq] = *(const uint4*)(Ab + (size_t)(lr+64) * SEQ + kw + lq);
            if (lr < 64)
                *(uint4*)&Vs[nb][lr][lq] = *(const uint4*)(Vb + (size_t)lr * SEQ + kw + lq);
        }
        #pragma unroll
        for (int c = 0; c < 2; c++) {
            const int cw = c * 8;
            unsigned af[2][4];
            #pragma unroll
            for (int mi = 0; mi < 2; mi++) {
                const int m0 = wm * 32 + mi * 16;
                ldsm4(af[mi][0], af[mi][1], af[mi][2], af[mi][3],
                      smaddr(&As[buf][m0 + arow][cw + asel]));
            }
            #pragma unroll
            for (int ni = 0; ni < 4; ni++) {
                const int n0 = wn * 32 + ni * 8;
                unsigned w0, w1;
                ldsm2(w0, w1, smaddr(&Vs[buf][n0 + brow][cw + bsel]));
                unsigned bd[2], bl[2];
                bd[0] = __byte_perm(w0, w0, 0x1010);
                bd[1] = __byte_perm(w1, w1, 0x1010);
                bl[0] = w0 >> 16;
                bl[1] = w1 >> 16;
                #pragma unroll
                for (int mi = 0; mi < 2; mi++) {
                    mma_bf16(acc[mi][ni], af[mi], bd);
                    mma_bf16(acc[mi][ni], af[mi], bl);
                }
            }
        }
        __syncthreads();
    }
    #pragma unroll
    for (int mi = 0; mi < 2; mi++)
        #pragma unroll
        for (int p = 0; p < 2; p++) {
            const size_t r = (size_t)(b * SEQ + qt * 128 + wm * 32 + mi * 16 + g + p * 8);
            #pragma unroll
            for (int ni = 0; ni < 4; ni++) {
                const int col = h * HD + wn * 32 + ni * 8 + 2 * tg;
                *(uint2*)(y + r * CH + col) =
                    make_uint2(splitw(acc[mi][ni][2*p+0]), splitw(acc[mi][ni][2*p+1]));
            }
        }
}

// ---------------- host launcher ----------------------------------------------
extern "C" void kernel_launch(void* const* d_in, const int* in_sizes, int n_in,
                              void* d_out, int out_size)
{
    const float* x     = (const float*)d_in[0];
    const float* ln1g  = (const float*)d_in[1];
    const float* ln1b  = (const float*)d_in[2];
    const float* attw  = (const float*)d_in[3];
    const float* attb  = (const float*)d_in[4];
    const float* projw = (const float*)d_in[5];
    const float* projb = (const float*)d_in[6];
    const float* ln2g  = (const float*)d_in[7];
    const float* ln2b  = (const float*)d_in[8];
    const float* fcw   = (const float*)d_in[9];
    const float* fcb   = (const float*)d_in[10];
    const float* fc2w  = (const float*)d_in[11];
    const float* fc2b  = (const float*)d_in[12];
    const float* lnfg  = (const float*)d_in[13];
    const float* lnfb  = (const float*)d_in[14];

    float *px;
    unsigned *plns, *pqkvs, *patt, *pvT, *py, *pfc;
    unsigned *pattwT, *pprojwT, *pfcwT, *pfc2wT;
    cudaGetSymbolAddress((void**)&px,      g_x);
    cudaGetSymbolAddress((void**)&plns,    g_lns);
    cudaGetSymbolAddress((void**)&pqkvs,   g_qkvs);
    cudaGetSymbolAddress((void**)&patt,    g_att);
    cudaGetSymbolAddress((void**)&pvT,     g_vT);
    cudaGetSymbolAddress((void**)&py,      g_y);
    cudaGetSymbolAddress((void**)&pfc,     g_fc);
    cudaGetSymbolAddress((void**)&pattwT,  g_attwT);
    cudaGetSymbolAddress((void**)&pprojwT, g_projwT);
    cudaGetSymbolAddress((void**)&pfcwT,   g_fcwT);
    cudaGetSymbolAddress((void**)&pfc2wT,  g_fc2wT);

    cudaFuncSetAttribute(gemmbf<false, false, true>,
                         cudaFuncAttributeMaxDynamicSharedMemorySize, GSMEM);
    cudaFuncSetAttribute(gemmbf<false, true, false>,
                         cudaFuncAttributeMaxDynamicSharedMemorySize, GSMEM);
    cudaFuncSetAttribute(gemmbf<true, false, true>,
                         cudaFuncAttributeMaxDynamicSharedMemorySize, GSMEM);

    const dim3 t32x8(32, 8);
    wsplit_k<<<dim3(CH/32, 3*CH/32, NLAYER), t32x8>>>(attw,  pattwT,  CH,   3*CH);
    wsplit_k<<<dim3(CH/32,   CH/32, NLAYER), t32x8>>>(projw, pprojwT, CH,   CH);
    wsplit_k<<<dim3(CH/32, 4*CH/32, NLAYER), t32x8>>>(fcw,   pfcwT,   CH,   4*CH);
    wsplit_k<<<dim3(4*CH/32, CH/32, NLAYER), t32x8>>>(fc2w,  pfc2wT,  4*CH, CH);

    copy_k<<<(MROWS * CH + 255) / 256, 256>>>(x, px, MROWS * CH);

    for (int l = 0; l < NLAYER; l++) {
        ln_k<true><<<MROWS, 256>>>(px, ln1g + l * CH, ln1b + l * CH, plns);
        gemmbf<false, false, true><<<dim3(3 * CH / 128, MROWS / 128), 256, GSMEM>>>(
            plns, pattwT + (size_t)l * 3 * CH * CH, attb + (size_t)l * 3 * CH,
            nullptr, pqkvs, 3 * CH, CH);
        vt_k<<<dim3(SEQ/32, CH/32, BATCH), t32x8>>>(pqkvs, pvT);
        attn_scores_bf<<<dim3(SEQ/128, SEQ/128, BATCH * NH), 256>>>(pqkvs, patt);
        softmax_w<<<BATCH * NH * SEQ, 128>>>(patt);
        attn_v_bf<<<dim3(SEQ/128, BATCH * NH), 256>>>(patt, pvT, py);
        gemmbf<false, true, false><<<dim3(CH / 128, MROWS / 128), 256, GSMEM>>>(
            py, pprojwT + (size_t)l * CH * CH, projb + (size_t)l * CH,
            px, px, CH, CH);
        ln_k<true><<<MROWS, 256>>>(px, ln2g + l * CH, ln2b + l * CH, plns);
        gemmbf<true, false, true><<<dim3(4 * CH / 128, MROWS / 128), 256, GSMEM>>>(
            plns, pfcwT + (size_t)l * 4 * CH * CH, fcb + (size_t)l * 4 * CH,
            nullptr, pfc, 4 * CH, CH);
        gemmbf<false, true, false><<<dim3(CH / 128, MROWS / 128), 256, GSMEM>>>(
            pfc, pfc2wT + (size_t)l * 4 * CH * CH, fc2b + (size_t)l * CH,
            px, px, CH, 4 * CH);
    }
    ln_k<false><<<MROWS, 256>>>(px, lnfg, lnfb, (float*)d_out);
}

// round 10
// speedup vs baseline: 2.0643x; 1.0245x over previous
#include <cuda_runtime.h>
#include <math.h>
#include <stdint.h>

#define NLAYER 12
#define BATCH  4
#define SEQ    1024
#define CH     1024
#define NH     16
#define HD     64
#define MROWS  (BATCH*SEQ)   // 4096
#define LNEPS  1e-5f
#define PIT    20            // attention smem word pitch
#define GP     36            // gemm smem word pitch
#define BKW    32            // gemm k-chunk in words

// ---------------- scratch (static device memory; no allocs allowed) ----------
__device__ float    g_x[MROWS*CH];
__device__ unsigned g_lns[MROWS*CH];
__device__ unsigned g_qkvs[(size_t)MROWS*3*CH];
__device__ unsigned g_att[(size_t)BATCH*NH*SEQ*SEQ];
__device__ unsigned g_vT[(size_t)BATCH*CH*SEQ];
__device__ unsigned g_y[MROWS*CH];
__device__ unsigned g_fc[(size_t)MROWS*4*CH];
__device__ unsigned g_attwT[(size_t)NLAYER*3*CH*CH];
__device__ unsigned g_projwT[(size_t)NLAYER*CH*CH];
__device__ unsigned g_fcwT[(size_t)NLAYER*4*CH*CH];
__device__ unsigned g_fc2wT[(size_t)NLAYER*4*CH*CH];

// ---------------- helpers -----------------------------------------------------
__device__ __forceinline__ unsigned splitw(float v) {          // hi | lo<<16
    unsigned u = __float_as_uint(v);
    unsigned hi = (u + 0x7fffu + ((u >> 16) & 1u)) >> 16;
    float hf = __uint_as_float(hi << 16);
    unsigned ul = __float_as_uint(v - hf);
    unsigned lo = (ul + 0x7fffu + ((ul >> 16) & 1u)) >> 16;
    return hi | (lo << 16);
}
__device__ __forceinline__ float unsplitw(unsigned w) {
    return __uint_as_float(w << 16) + __uint_as_float(w & 0xffff0000u);
}
__device__ __forceinline__ void mma_bf16(float* c, const unsigned* a, const unsigned* b) {
    asm volatile("mma.sync.aligned.m16n8k16.row.col.f32.bf16.bf16.f32 "
        "{%0,%1,%2,%3}, {%4,%5,%6,%7}, {%8,%9}, {%0,%1,%2,%3};\n"
        : "+f"(c[0]), "+f"(c[1]), "+f"(c[2]), "+f"(c[3])
        : "r"(a[0]), "r"(a[1]), "r"(a[2]), "r"(a[3]), "r"(b[0]), "r"(b[1]));
}
__device__ __forceinline__ float gelu1(float v) {
    const float kk = 0.7978845608028654f;
    return 0.5f * v * (1.f + tanhf(kk * (v + 0.044715f * v * v * v)));
}
__device__ __forceinline__ uint32_t smaddr(const void* p) {
    uint32_t u;
    asm("{ .reg .u64 t; cvta.to.shared.u64 t, %1; cvt.u32.u64 %0, t; }" : "=r"(u) : "l"(p));
    return u;
}
__device__ __forceinline__ void ldsm4(unsigned& r0, unsigned& r1, unsigned& r2,
                                      unsigned& r3, uint32_t a) {
    asm volatile("ldmatrix.sync.aligned.m8n8.x4.shared.b16 {%0,%1,%2,%3}, [%4];"
                 : "=r"(r0), "=r"(r1), "=r"(r2), "=r"(r3) : "r"(a));
}
__device__ __forceinline__ void ldsm2(unsigned& r0, unsigned& r1, uint32_t a) {
    asm volatile("ldmatrix.sync.aligned.m8n8.x2.shared.b16 {%0,%1}, [%2];"
                 : "=r"(r0), "=r"(r1) : "r"(a));
}
__device__ __forceinline__ void cpa16(uint32_t dst, const void* src) {
    asm volatile("cp.async.cg.shared.global [%0], [%1], 16;" :: "r"(dst), "l"(src));
}
__device__ __forceinline__ void cpcommit() { asm volatile("cp.async.commit_group;"); }
template<int N> __device__ __forceinline__ void cpwait() {
    asm volatile("cp.async.wait_group %0;" :: "n"(N));
}

// ---------------- zero / copy -------------------------------------------------
__global__ void zero_k(unsigned* __restrict__ p, size_t n) {
    size_t i = (size_t)blockIdx.x * blockDim.x + threadIdx.x;
    if (i < n) p[i] = 0u;
}
__global__ void copy_k(const float* __restrict__ in, float* __restrict__ out, int n) {
    int i = blockIdx.x * blockDim.x + threadIdx.x;
    if (i < n) out[i] = in[i];
}

// ---------------- weight split + transpose ------------------------------------
__global__ void wsplit_k(const float* __restrict__ W, unsigned* __restrict__ WT,
                         int K, int N) {
    __shared__ unsigned sm[32][33];
    const int l = blockIdx.z;
    const float* Wl = W + (size_t)l * K * N;
    unsigned* WTl = WT + (size_t)l * K * N;
    const int k0 = blockIdx.x * 32, n0 = blockIdx.y * 32;
    const int tx = threadIdx.x, ty = threadIdx.y;
    #pragma unroll
    for (int i = 0; i < 4; i++)
        sm[ty + 8*i][tx] = splitw(Wl[(size_t)(k0 + ty + 8*i) * N + n0 + tx]);
    __syncthreads();
    #pragma unroll
    for (int i = 0; i < 4; i++)
        WTl[(size_t)(n0 + ty + 8*i) * K + k0 + tx] = sm[tx][ty + 8*i];
}

// ---------------- V transpose ------------------------------------------------
__global__ void vt_k(const unsigned* __restrict__ qkvs, unsigned* __restrict__ vT) {
    __shared__ unsigned sm[32][33];
    const int b = blockIdx.z;
    const int s0 = blockIdx.x * 32, c0 = blockIdx.y * 32;
    const int tx = threadIdx.x, ty = threadIdx.y;
    #pragma unroll
    for (int i = 0; i < 4; i++)
        sm[ty + 8*i][tx] = qkvs[(size_t)(b * SEQ + s0 + ty + 8*i) * (3*CH) + 2*CH + c0 + tx];
    __syncthreads();
    #pragma unroll
    for (int i = 0; i < 4; i++)
        vT[(size_t)(b * CH + c0 + ty + 8*i) * SEQ + s0 + tx] = sm[tx][ty + 8*i];
}

// ---------------- layernorm --------------------------------------------------
template<bool SPLIT>
__global__ void ln_k(const float* __restrict__ in, const float* __restrict__ gam,
                     const float* __restrict__ bet, void* __restrict__ outv) {
    int row = blockIdx.x;
    const float* p = in + (size_t)row * CH;
    float s = 0.f, s2 = 0.f;
    for (int c = threadIdx.x; c < CH; c += blockDim.x) {
        float v = p[c];
        s += v; s2 += v * v;
    }
    __shared__ float sh[16];
    #pragma unroll
    for (int o = 16; o > 0; o >>= 1) {
        s  += __shfl_down_sync(0xffffffffu, s, o);
        s2 += __shfl_down_sync(0xffffffffu, s2, o);
    }
    int lane = threadIdx.x & 31, w = threadIdx.x >> 5;
    if (lane == 0) { sh[w] = s; sh[8 + w] = s2; }
    __syncthreads();
    if (threadIdx.x == 0) {
        float a = 0.f, b = 0.f;
        #pragma unroll
        for (int i = 0; i < 8; i++) { a += sh[i]; b += sh[8 + i]; }
        sh[0] = a; sh[8] = b;
    }
    __syncthreads();
    float mean = sh[0] * (1.f / CH);
    float var  = sh[8] * (1.f / CH) - mean * mean;
    float rstd = rsqrtf(var + LNEPS);
    for (int c = threadIdx.x; c < CH; c += blockDim.x) {
        float v = (p[c] - mean) * rstd * gam[c] + bet[c];
        if (SPLIT) ((unsigned*)outv)[(size_t)row * CH + c] = splitw(v);
        else       ((float*)outv)[(size_t)row * CH + c] = v;
    }
}

// ---------------- bf16 compensated GEMM (cp.async + ldmatrix) ----------------
#define GSMEM (2*128*GP*4*2)   // 73728 B

template<bool DO_GELU, bool DO_RES, bool OUT_SPLIT>
__global__ void __launch_bounds__(256, 2) gemmbf(
    const unsigned* __restrict__ A, const unsigned* __restrict__ Bt,
    const float* __restrict__ bias, const float* __restrict__ Res,
    void* __restrict__ Cv, int N, int K)
{
    extern __shared__ unsigned sm[];
    unsigned* As = sm;                 // [2][128][GP]
    unsigned* Bs = sm + 2 * 128 * GP;
    const int tid = threadIdx.x;
    const int row0 = blockIdx.y * 128, col0 = blockIdx.x * 128;
    const int warp = tid >> 5, lane = tid & 31;
    const int wm = warp >> 2, wn = warp & 3;
    const int g = lane >> 2, tg = lane & 3;
    const int ldr = tid >> 3, ldc = (tid & 7) << 2;

    float acc[4][4][4] = {};

    const int arow = lane & 15, asel = (lane >> 4) << 2;
    const int brow = lane & 7,  bsel = ((lane >> 3) & 1) << 2;

    auto load_stage = [&](int s, int kw) {
        unsigned* Ad = As + s * 128 * GP;
        unsigned* Bd = Bs + s * 128 * GP;
        #pragma unroll
        for (int j = 0; j < 4; j++) {
            int r = ldr + j * 32;
            cpa16(smaddr(Ad + r * GP + ldc), A  + (size_t)(row0 + r) * K + kw + ldc);
        }
        #pragma unroll
        for (int j = 0; j < 4; j++) {
            int r = ldr + j * 32;
            cpa16(smaddr(Bd + r * GP + ldc), Bt + (size_t)(col0 + r) * K + kw + ldc);
        }
        cpcommit();
    };

    load_stage(0, 0);
    load_stage(1, BKW);

    const int nk = K >> 5;
    for (int kt = 0; kt < nk; kt++) {
        const int s = kt & 1;
        cpwait<1>();
        __syncthreads();
        const unsigned* Ab = As + s * 128 * GP;
        const unsigned* Bb = Bs + s * 128 * GP;
        #pragma unroll
        for (int c = 0; c < 4; c++) {
            const int cw = c * 8;
            unsigned af[4][4];
            #pragma unroll
            for (int mi = 0; mi < 4; mi++) {
                const int m0 = wm * 64 + mi * 16;
                ldsm4(af[mi][0], af[mi][1], af[mi][2], af[mi][3],
                      smaddr(Ab + (m0 + arow) * GP + cw + asel));
            }
            // process ni pairs: build variants, then bd-sweep, then bl-sweep
            #pragma unroll
            for (int nh = 0; nh < 2; nh++) {
                unsigned bd[2][2], bl[2][2];
                #pragma unroll
                for (int u = 0; u < 2; u++) {
                    const int n0 = (wn * 4 + nh * 2 + u) * 8;
                    unsigned w0, w1;
                    ldsm2(w0, w1, smaddr(Bb + (n0 + brow) * GP + cw + bsel));
                    bd[u][0] = __byte_perm(w0, w0, 0x1010);
                    bd[u][1] = __byte_perm(w1, w1, 0x1010);
                    bl[u][0] = w0 >> 16;
                    bl[u][1] = w1 >> 16;
                }
                #pragma unroll
                for (int u = 0; u < 2; u++)
                    #pragma unroll
                    for (int mi = 0; mi < 4; mi++)
                        mma_bf16(acc[mi][nh * 2 + u], af[mi], bd[u]);
                #pragma unroll
                for (int u = 0; u < 2; u++)
                    #pragma unroll
                    for (int mi = 0; mi < 4; mi++)
                        mma_bf16(acc[mi][nh * 2 + u], af[mi], bl[u]);
            }
        }
        __syncthreads();
        if (kt + 2 < nk) load_stage(s, (kt + 2) * BKW);
    }

    // epilogue
    #pragma unroll
    for (int mi = 0; mi < 4; mi++) {
        #pragma unroll
        for (int p = 0; p < 2; p++) {
            const size_t r = (size_t)(row0 + wm * 64 + mi * 16 + g + p * 8);
            #pragma unroll
            for (int ni = 0; ni < 4; ni++) {
                const int col = col0 + wn * 32 + ni * 8 + 2 * tg;
                float2 bv = *(const float2*)(bias + col);
                float v0 = acc[mi][ni][2*p+0] + bv.x;
                float v1 = acc[mi][ni][2*p+1] + bv.y;
                if (DO_GELU) { v0 = gelu1(v0); v1 = gelu1(v1); }
                if (DO_RES) {
                    float2 rv = *(const float2*)(Res + r * N + col);
                    v0 += rv.x; v1 += rv.y;
                }
                if (OUT_SPLIT)
                    *(uint2*)((unsigned*)Cv + r * N + col) =
                        make_uint2(splitw(v0), splitw(v1));
                else
                    *(float2*)((float*)Cv + r * N + col) = make_float2(v0, v1);
            }
        }
    }
}

// ---------------- attention scores (compensated bf16, ldmatrix) --------------
__global__ void __launch_bounds__(256, 2) attn_scores_bf(
    const unsigned* __restrict__ qkvs, unsigned* __restrict__ att)
{
    const int bh = blockIdx.z, b = bh >> 4, h = bh & 15;
    const int qt = blockIdx.y, kt = blockIdx.x;
    if (kt > qt) return;

    __shared__ unsigned Qs[2][128][PIT];
    __shared__ unsigned Ks[2][128][PIT];
    const int tid = threadIdx.x;
    const int warp = tid >> 5, lane = tid & 31;
    const int wm = warp >> 2, wn = warp & 3;
    const int g = lane >> 2, tg = lane & 3;
    const int lr = tid >> 2, lq = (tid & 3) << 2;
    const int arow = lane & 15, asel = (lane >> 4) << 2;
    const int brow = lane & 7,  bsel = ((lane >> 3) & 1) << 2;
    const size_t RS = 3 * CH;
    const unsigned* Qb = qkvs + (size_t)(b * SEQ + qt * 128) * RS + h * HD;
    const unsigned* Kb = qkvs + (size_t)(b * SEQ + kt * 128) * RS + CH + h * HD;

    float acc[4][4][4] = {};
    {
        *(uint4*)&Qs[0][lr][lq]    = *(const uint4*)(Qb + (size_t)lr * RS + lq);
        *(uint4*)&Qs[0][lr+64][lq] = *(const uint4*)(Qb + (size_t)(lr+64) * RS + lq);
        *(uint4*)&Ks[0][lr][lq]    = *(const uint4*)(Kb + (size_t)lr * RS + lq);
        *(uint4*)&Ks[0][lr+64][lq] = *(const uint4*)(Kb + (size_t)(lr+64) * RS + lq);
    }
    __syncthreads();
    const int nk = HD >> 4;
    for (int dt = 0; dt < nk; dt++) {
        const int buf = dt & 1;
        if (dt + 1 < nk) {
            const int nb = buf ^ 1, kw = (dt + 1) << 4;
            *(uint4*)&Qs[nb][lr][lq]    = *(const uint4*)(Qb + (size_t)lr * RS + kw + lq);
            *(uint4*)&Qs[nb][lr+64][lq] = *(const uint4*)(Qb + (size_t)(lr+64) * RS + kw + lq);
            *(uint4*)&Ks[nb][lr][lq]    = *(const uint4*)(Kb + (size_t)lr * RS + kw + lq);
            *(uint4*)&Ks[nb][lr+64][lq] = *(const uint4*)(Kb + (size_t)(lr+64) * RS + kw + lq);
        }
        #pragma unroll
        for (int c = 0; c < 2; c++) {
            const int cw = c * 8;
            unsigned af[4][4];
            #pragma unroll
            for (int mi = 0; mi < 4; mi++) {
                const int m0 = wm * 64 + mi * 16;
                ldsm4(af[mi][0], af[mi][1], af[mi][2], af[mi][3],
                      smaddr(&Qs[buf][m0 + arow][cw + asel]));
            }
            #pragma unroll
            for (int nh = 0; nh < 2; nh++) {
                unsigned bd[2][2], bl[2][2];
                #pragma unroll
                for (int u = 0; u < 2; u++) {
                    const int n0 = (wn * 4 + nh * 2 + u) * 8;
                    unsigned w0, w1;
                    ldsm2(w0, w1, smaddr(&Ks[buf][n0 + brow][cw + bsel]));
                    bd[u][0] = __byte_perm(w0, w0, 0x1010);
                    bd[u][1] = __byte_perm(w1, w1, 0x1010);
                    bl[u][0] = w0 >> 16;
                    bl[u][1] = w1 >> 16;
                }
                #pragma unroll
                for (int u = 0; u < 2; u++)
                    #pragma unroll
                    for (int mi = 0; mi < 4; mi++)
                        mma_bf16(acc[mi][nh * 2 + u], af[mi], bd[u]);
                #pragma unroll
                for (int u = 0; u < 2; u++)
                    #pragma unroll
                    for (int mi = 0; mi < 4; mi++)
                        mma_bf16(acc[mi][nh * 2 + u], af[mi], bl[u]);
            }
        }
        __syncthreads();
    }
    const bool diag = (qt == kt);
    const float scale = 0.125f;
    #pragma unroll
    for (int mi = 0; mi < 4; mi++)
        #pragma unroll
        for (int p = 0; p < 2; p++) {
            const int q = qt * 128 + wm * 64 + mi * 16 + g + p * 8;
            unsigned* rowp = att + ((size_t)bh * SEQ + q) * SEQ + kt * 128;
            #pragma unroll
            for (int ni = 0; ni < 4; ni++) {
                const int kc = wn * 32 + ni * 8 + 2 * tg;
                unsigned w0 = splitw(acc[mi][ni][2*p+0] * scale);
                unsigned w1 = splitw(acc[mi][ni][2*p+1] * scale);
                if (!diag) {
                    *(uint2*)(rowp + kc) = make_uint2(w0, w1);
                } else {
                    const int kg = kt * 128 + kc;
                    if (kg     <= q) rowp[kc]     = w0;
                    if (kg + 1 <= q) rowp[kc + 1] = w1;
                }
            }
        }
}

// ---------------- causal softmax (masked tail pre-zeroed once) ---------------
__global__ void softmax_w(unsigned* __restrict__ att) {
    const int row = blockIdx.x;
    const int q = row & (SEQ - 1);
    unsigned* p = att + (size_t)row * SEQ;
    const int n = q + 1;
    const int tid = threadIdx.x;

    float m = -1e30f;
    for (int j = tid; j < n; j += blockDim.x) m = fmaxf(m, unsplitw(p[j]));
    __shared__ float shm[4], shs[4];
    #pragma unroll
    for (int o = 16; o > 0; o >>= 1) m = fmaxf(m, __shfl_xor_sync(0xffffffffu, m, o));
    if ((tid & 31) == 0) shm[tid >> 5] = m;
    __syncthreads();
    m = fmaxf(fmaxf(shm[0], shm[1]), fmaxf(shm[2], shm[3]));

    float s = 0.f;
    for (int j = tid; j < n; j += blockDim.x) {
        float e = __expf(unsplitw(p[j]) - m);
        p[j] = splitw(e); s += e;
    }
    #pragma unroll
    for (int o = 16; o > 0; o >>= 1) s += __shfl_xor_sync(0xffffffffu, s, o);
    if ((tid & 31) == 0) shs[tid >> 5] = s;
    __syncthreads();
    s = shs[0] + shs[1] + shs[2] + shs[3];
    float inv = 1.f / s;
    for (int j = tid; j < n; j += blockDim.x) p[j] = splitw(unsplitw(p[j]) * inv);
}

// ---------------- att @ V (compensated bf16, ldmatrix) -----------------------
__global__ void __launch_bounds__(256, 2) attn_v_bf(
    const unsigned* __restrict__ att, const unsigned* __restrict__ vT,
    unsigned* __restrict__ y)
{
    const int qt = blockIdx.x, bh = blockIdx.y;
    const int b = bh >> 4, h = bh & 15;
    __shared__ unsigned As[2][128][PIT];
    __shared__ unsigned Vs[2][64][PIT];
    const int tid = threadIdx.x;
    const int warp = tid >> 5, lane = tid & 31;
    const int wm = warp >> 1, wn = warp & 1;
    const int g = lane >> 2, tg = lane & 3;
    const int lr = tid >> 2, lq = (tid & 3) << 2;
    const int arow = lane & 15, asel = (lane >> 4) << 2;
    const int brow = lane & 7,  bsel = ((lane >> 3) & 1) << 2;
    const unsigned* Ab = att + (size_t)(bh * SEQ + qt * 128) * SEQ;
    const unsigned* Vb = vT + (size_t)bh * HD * SEQ;

    float acc[2][4][4] = {};
    {
        *(uint4*)&As[0][lr][lq]    = *(const uint4*)(Ab + (size_t)lr * SEQ + lq);
        *(uint4*)&As[0][lr+64][lq] = *(const uint4*)(Ab + (size_t)(lr+64) * SEQ + lq);
        *(uint4*)&Vs[0][lr & 63][lq] = *(const uint4*)(Vb + (size_t)(lr & 63) * SEQ + lq);
    }
    __syncthreads();
    const int nkt = (qt + 1) * 8;
    for (int kt = 0; kt < nkt; kt++) {
        const int buf = kt & 1;
        if (kt + 1 < nkt) {
            const int nb = buf ^ 1, kw = (kt + 1) << 4;
            *(uint4*)&As[nb][lr][lq]    = *(const uint4*)(Ab + (size_t)lr * SEQ + kw + lq);
            *(uint4*)&As[nb][lr+64][lq] = *(const uint4*)(Ab + (size_t)(lr+64) * SEQ + kw + lq);
            if (lr < 64)
                *(uint4*)&Vs[nb][lr][lq] = *(const uint4*)(Vb + (size_t)lr * SEQ + kw + lq);
        }
        #pragma unroll
        for (int c = 0; c < 2; c++) {
            const int cw = c * 8;
            unsigned af[2][4], bd[4][2], bl[4][2];
            #pragma unroll
            for (int mi = 0; mi < 2; mi++) {
                const int m0 = wm * 32 + mi * 16;
                ldsm4(af[mi][0], af[mi][1], af[mi][2], af[mi][3],
                      smaddr(&As[buf][m0 + arow][cw + asel]));
            }
            #pragma unroll
            for (int ni = 0; ni < 4; ni++) {
                const int n0 = wn * 32 + ni * 8;
                unsigned w0, w1;
                ldsm2(w0, w1, smaddr(&Vs[buf][n0 + brow][cw + bsel]));
                bd[ni][0] = __byte_perm(w0, w0, 0x1010);
                bd[ni][1] = __byte_perm(w1, w1, 0x1010);
                bl[ni][0] = w0 >> 16;
                bl[ni][1] = w1 >> 16;
            }
            #pragma unroll
            for (int ni = 0; ni < 4; ni++)
                #pragma unroll
                for (int mi = 0; mi < 2; mi++)
                    mma_bf16(acc[mi][ni], af[mi], bd[ni]);
            #pragma unroll
            for (int ni = 0; ni < 4; ni++)
                #pragma unroll
                for (int mi = 0; mi < 2; mi++)
                    mma_bf16(acc[mi][ni], af[mi], bl[ni]);
        }
        __syncthreads();
    }
    #pragma unroll
    for (int mi = 0; mi < 2; mi++)
        #pragma unroll
        for (int p = 0; p < 2; p++) {
            const size_t r = (size_t)(b * SEQ + qt * 128 + wm * 32 + mi * 16 + g + p * 8);
            #pragma unroll
            for (int ni = 0; ni < 4; ni++) {
                const int col = h * HD + wn * 32 + ni * 8 + 2 * tg;
                *(uint2*)(y + r * CH + col) =
                    make_uint2(splitw(acc[mi][ni][2*p+0]), splitw(acc[mi][ni][2*p+1]));
            }
        }
}

// ---------------- host launcher ----------------------------------------------
extern "C" void kernel_launch(void* const* d_in, const int* in_sizes, int n_in,
                              void* d_out, int out_size)
{
    const float* x     = (const float*)d_in[0];
    const float* ln1g  = (const float*)d_in[1];
    const float* ln1b  = (const float*)d_in[2];
    const float* attw  = (const float*)d_in[3];
    const float* attb  = (const float*)d_in[4];
    const float* projw = (const float*)d_in[5];
    const float* projb = (const float*)d_in[6];
    const float* ln2g  = (const float*)d_in[7];
    const float* ln2b  = (const float*)d_in[8];
    const float* fcw   = (const float*)d_in[9];
    const float* fcb   = (const float*)d_in[10];
    const float* fc2w  = (const float*)d_in[11];
    const float* fc2b  = (const float*)d_in[12];
    const float* lnfg  = (const float*)d_in[13];
    const float* lnfb  = (const float*)d_in[14];

    float *px;
    unsigned *plns, *pqkvs, *patt, *pvT, *py, *pfc;
    unsigned *pattwT, *pprojwT, *pfcwT, *pfc2wT;
    cudaGetSymbolAddress((void**)&px,      g_x);
    cudaGetSymbolAddress((void**)&plns,    g_lns);
    cudaGetSymbolAddress((void**)&pqkvs,   g_qkvs);
    cudaGetSymbolAddress((void**)&patt,    g_att);
    cudaGetSymbolAddress((void**)&pvT,     g_vT);
    cudaGetSymbolAddress((void**)&py,      g_y);
    cudaGetSymbolAddress((void**)&pfc,     g_fc);
    cudaGetSymbolAddress((void**)&pattwT,  g_attwT);
    cudaGetSymbolAddress((void**)&pprojwT, g_projwT);
    cudaGetSymbolAddress((void**)&pfcwT,   g_fcwT);
    cudaGetSymbolAddress((void**)&pfc2wT,  g_fc2wT);

    cudaFuncSetAttribute(gemmbf<false, false, true>,
                         cudaFuncAttributeMaxDynamicSharedMemorySize, GSMEM);
    cudaFuncSetAttribute(gemmbf<false, true, false>,
                         cudaFuncAttributeMaxDynamicSharedMemorySize, GSMEM);
    cudaFuncSetAttribute(gemmbf<true, false, true>,
                         cudaFuncAttributeMaxDynamicSharedMemorySize, GSMEM);

    const dim3 t32x8(32, 8);
    wsplit_k<<<dim3(CH/32, 3*CH/32, NLAYER), t32x8>>>(attw,  pattwT,  CH,   3*CH);
    wsplit_k<<<dim3(CH/32,   CH/32, NLAYER), t32x8>>>(projw, pprojwT, CH,   CH);
    wsplit_k<<<dim3(CH/32, 4*CH/32, NLAYER), t32x8>>>(fcw,   pfcwT,   CH,   4*CH);
    wsplit_k<<<dim3(4*CH/32, CH/32, NLAYER), t32x8>>>(fc2w,  pfc2wT,  4*CH, CH);

    // zero attention buffer once — masked tail (k>q) stays zero all layers
    {
        size_t n = (size_t)BATCH * NH * SEQ * SEQ;
        zero_k<<<(unsigned)((n + 511) / 512), 512>>>(patt, n);
    }
    copy_k<<<(MROWS * CH + 255) / 256, 256>>>(x, px, MROWS * CH);

    for (int l = 0; l < NLAYER; l++) {
        ln_k<true><<<MROWS, 256>>>(px, ln1g + l * CH, ln1b + l * CH, plns);
        gemmbf<false, false, true><<<dim3(3 * CH / 128, MROWS / 128), 256, GSMEM>>>(
            plns, pattwT + (size_t)l * 3 * CH * CH, attb + (size_t)l * 3 * CH,
            nullptr, pqkvs, 3 * CH, CH);
        vt_k<<<dim3(SEQ/32, CH/32, BATCH), t32x8>>>(pqkvs, pvT);
        attn_scores_bf<<<dim3(SEQ/128, SEQ/128, BATCH * NH), 256>>>(pqkvs, patt);
        softmax_w<<<BATCH * NH * SEQ, 128>>>(patt);
        attn_v_bf<<<dim3(SEQ/128, BATCH * NH), 256>>>(patt, pvT, py);
        gemmbf<false, true, false><<<dim3(CH / 128, MROWS / 128), 256, GSMEM>>>(
            py, pprojwT + (size_t)l * CH * CH, projb + (size_t)l * CH,
            px, px, CH, CH);
        ln_k<true><<<MROWS, 256>>>(px, ln2g + l * CH, ln2b + l * CH, plns);
        gemmbf<true, false, true><<<dim3(4 * CH / 128, MROWS / 128), 256, GSMEM>>>(
            plns, pfcwT + (size_t)l * 4 * CH * CH, fcb + (size_t)l * 4 * CH,
            nullptr, pfc, 4 * CH, CH);
        gemmbf<false, true, false><<<dim3(CH / 128, MROWS / 128), 256, GSMEM>>>(
            pfc, pfc2wT + (size_t)l * 4 * CH * CH, fc2b + (size_t)l * CH,
            px, px, CH, 4 * CH);
    }
    ln_k<false><<<MROWS, 256>>>(px, lnfg, lnfb, (float*)d_out);
}